// round 4
// baseline (speedup 1.0000x reference)
#include <cuda_runtime.h>
#include <cstdint>
#include <cstddef>

#define NA 2048
#define HH 128
#define NE 32768
#define RR 32
#define NH (NA*HH)
#define CUT 4.5f

// ---------------- scratch (static device globals; no allocations) ----------------
__device__ float g_ea[NE*384];      // edge MLP output, layout [e][3][128]
__device__ float g_Xn[NH*9];        // normalized X
__device__ float g_cA[9*NH];        // compact planes of Xn (pre-mix)
__device__ float g_cM[9*NH];        // compact planes after chan_mix
__device__ float g_c2[9*NH];        // compact planes of scaled/normalized AB
__device__ float g_dXc[9*NH];       // compact planes of dX
__device__ float g_W1hl[2*128*32*2];    // [l][o][k]{hi,lo}
__device__ float g_W2hl[2*256*128*2];   // [l][o][k]{hi,lo}
__device__ float g_W3hl[2*384*256*2];   // [l][o'][k]{hi,lo}, o' = c*128+h
__device__ float g_WtT[12*HH*HH];       // [l*6+m][h][g]
__device__ int   g_cnt[NA];
__device__ int   g_cur[NA];
__device__ int   g_row[NA+1];
__device__ int   g_eord[NE];

typedef unsigned long long u64;

// ---------------- generic helpers ----------------
__device__ __forceinline__ u64 pk(float a, float b){
    u64 r; asm("mov.b64 %0, {%1,%2};" : "=l"(r) : "f"(a), "f"(b)); return r;
}
__device__ __forceinline__ void upk(u64 v, float& a, float& b){
    asm("mov.b64 {%0,%1}, %2;" : "=f"(a), "=f"(b) : "l"(v));
}
__device__ __forceinline__ void fma2(u64& d, u64 a, u64 b){
    asm("fma.rn.f32x2 %0, %1, %2, %0;" : "+l"(d) : "l"(a), "l"(b));
}
__device__ __forceinline__ float siluf(float x){ return x / (1.f + __expf(-x)); }
__device__ __forceinline__ float tf32r(float x){
    uint32_t u; asm("cvt.rna.tf32.f32 %0, %1;" : "=r"(u) : "f"(x));
    return __uint_as_float(u);
}

// m16n8k8 tf32 mma: D(16x8) += A(16x8,row) * B(8x8,col)
__device__ __forceinline__ void mma8(float* d, const uint32_t* a, const uint32_t* b){
    asm volatile("mma.sync.aligned.m16n8k8.row.col.f32.tf32.tf32.f32 "
        "{%0,%1,%2,%3}, {%4,%5,%6,%7}, {%8,%9}, {%0,%1,%2,%3};"
        : "+f"(d[0]),"+f"(d[1]),"+f"(d[2]),"+f"(d[3])
        : "r"(a[0]),"r"(a[1]),"r"(a[2]),"r"(a[3]), "r"(b[0]),"r"(b[1]));
}

// split an fp32 value into two canonical-tf32 parts (hi via mantissa truncation)
__device__ __forceinline__ void splitb(float v, uint32_t& h, uint32_t& lo){
    uint32_t u = __float_as_uint(v);
    h = u & 0xFFFFE000u;
    float r = v - __uint_as_float(h);
    lo = __float_as_uint(r) & 0xFFFFE000u;
}

// compact basis: {i0, a01, a02, a12, s00, s01, s02, s11, s12}
__device__ __forceinline__ void tocompact(const float* t, float s, float* c){
    float i0 = (t[0]+t[4]+t[8])*(1.f/3.f);
    c[0] = i0*s;
    c[1] = 0.5f*(t[1]-t[3])*s;
    c[2] = 0.5f*(t[2]-t[6])*s;
    c[3] = 0.5f*(t[5]-t[7])*s;
    c[4] = (t[0]-i0)*s;
    c[5] = 0.5f*(t[1]+t[3])*s;
    c[6] = 0.5f*(t[2]+t[6])*s;
    c[7] = (t[4]-i0)*s;
    c[8] = 0.5f*(t[5]+t[7])*s;
}
__device__ __forceinline__ void rec(const float* c, float* t){
    float i0=c[0], a01=c[1], a02=c[2], a12=c[3];
    float s00=c[4], s01=c[5], s02=c[6], s11=c[7], s12=c[8];
    t[0]=i0+s00;  t[1]=a01+s01; t[2]=a02+s02;
    t[3]=s01-a01; t[4]=i0+s11;  t[5]=a12+s12;
    t[6]=s02-a02; t[7]=s12-a12; t[8]=i0-s00-s11;
}
__device__ __forceinline__ void mmadd(const float* A, const float* B, float* C){
    #pragma unroll
    for(int i=0;i<3;i++){
        #pragma unroll
        for(int j=0;j<3;j++)
            C[i*3+j] += A[i*3+0]*B[0*3+j] + A[i*3+1]*B[1*3+j] + A[i*3+2]*B[2*3+j];
    }
}

// ---------------- weight prep: hi/lo tf32 splits + WtT transpose ----------------
__global__ void k_prep_w(const float* __restrict__ Ws1, const float* __restrict__ Ws2,
                         const float* __restrict__ Ws3, const float* __restrict__ Wt){
    int stride = gridDim.x*blockDim.x;
    int t0 = blockIdx.x*blockDim.x + threadIdx.x;
    for(int i=t0;i<2*128*32;i+=stride){
        float w = Ws1[i]; float hi = tf32r(w);
        g_W1hl[i*2]=hi; g_W1hl[i*2+1]=tf32r(w-hi);
    }
    for(int i=t0;i<2*256*128;i+=stride){
        float w = Ws2[i]; float hi = tf32r(w);
        g_W2hl[i*2]=hi; g_W2hl[i*2+1]=tf32r(w-hi);
    }
    // W3 with output-row permutation: src row j = h*3+c  ->  dst row o' = c*128+h
    for(int i=t0;i<2*384*256;i+=stride){
        int l=i/98304, r=i%98304, j=r/256, k=r%256;
        int op = (j%3)*128 + j/3;
        float w = Ws3[i]; float hi = tf32r(w);
        int di = (l*98304 + op*256 + k)*2;
        g_W3hl[di]=hi; g_W3hl[di+1]=tf32r(w-hi);
    }
    for(int i=t0;i<12*128*128;i+=stride){
        int lm=i/16384, r=i%16384, g=r/128, hh=r%128;
        g_WtT[lm*16384 + hh*128 + g] = Wt[i];
    }
}

// ---------------- CSR build ----------------
__global__ void k_zero_cnt(){
    int i = blockIdx.x*blockDim.x + threadIdx.x;
    if(i<NA){ g_cnt[i]=0; g_cur[i]=0; }
}
__global__ void k_count(const int* __restrict__ ei){
    int e = blockIdx.x*blockDim.x + threadIdx.x;
    if(e<NE) atomicAdd(&g_cnt[ei[e]], 1);
}
__global__ void k_scan(){
    __shared__ int sh[1024];
    int t = threadIdx.x;
    int v0 = g_cnt[2*t], v1 = g_cnt[2*t+1];
    int s = v0+v1;
    sh[t]=s; __syncthreads();
    #pragma unroll
    for(int off=1; off<1024; off<<=1){
        int x = (t>=off)? sh[t-off] : 0;
        __syncthreads();
        sh[t] += x;
        __syncthreads();
    }
    int incl = sh[t];
    int excl = incl - s;
    g_row[2*t]   = excl;
    g_row[2*t+1] = excl + v0;
    if(t==1023) g_row[2048]=incl;
}
__global__ void k_place(const int* __restrict__ ei){
    int e = blockIdx.x*blockDim.x + threadIdx.x;
    if(e<NE){
        int s = ei[e];
        int p = atomicAdd(&g_cur[s],1);
        g_eord[g_row[s]+p] = e;
    }
}

// ---------------- node prep: normalize + compact decompose ----------------
__global__ void k_node_prep(const float* __restrict__ Xin){
    int idx = blockIdx.x*blockDim.x + threadIdx.x;
    if(idx>=NH) return;
    float t[9]; float nrm=0.f;
    #pragma unroll
    for(int r=0;r<9;r++){ t[r]=Xin[(size_t)idx*9+r]; nrm += t[r]*t[r]; }
    float inv = 1.f/(nrm+1.f);
    #pragma unroll
    for(int r=0;r<9;r++){ t[r]*=inv; g_Xn[(size_t)idx*9+r]=t[r]; }
    float c[9]; tocompact(t,1.f,c);
    #pragma unroll
    for(int d=0;d<9;d++) g_cA[d*NH+idx]=c[d];
}

// ---------------- channel mix (f32x2) ----------------
__global__ void __launch_bounds__(128) k_mix(int which, int wbase){
    __shared__ float sin_[32*128];
    const float* in  = which ? g_c2  : g_cA;
    float*       out = which ? g_dXc : g_cM;
    int d = blockIdx.y;
    int m = (d==0)?0:((d<4)?1:2);
    const float* W = g_WtT + (size_t)(wbase+m)*16384;
    int n0 = blockIdx.x*32;
    const float* src = in + (size_t)d*NH + (size_t)n0*HH;
    for(int i=threadIdx.x;i<1024;i+=128)
        ((float4*)sin_)[i] = ((const float4*)src)[i];
    __syncthreads();
    int w = threadIdx.x>>5, lane = threadIdx.x&31;
    u64 acc[8][2];
    #pragma unroll
    for(int i=0;i<8;i++){ acc[i][0]=0ull; acc[i][1]=0ull; }
    for(int k=0;k<128;k++){
        float4 wf = *(const float4*)&W[k*128 + lane*4];
        u64 w0=pk(wf.x,wf.y), w1=pk(wf.z,wf.w);
        #pragma unroll
        for(int i=0;i<8;i++){
            float v = sin_[(w*8+i)*128 + k];
            u64 vp = pk(v,v);
            fma2(acc[i][0],vp,w0); fma2(acc[i][1],vp,w1);
        }
    }
    float* dst = out + (size_t)d*NH + (size_t)n0*HH;
    #pragma unroll
    for(int i=0;i<8;i++){
        float4 o; upk(acc[i][0],o.x,o.y); upk(acc[i][1],o.z,o.w);
        *(float4*)&dst[(w*8+i)*HH + lane*4] = o;
    }
}

// ---------------- edge MLP via mma.sync tf32 (hi/lo compensated) ----------------
// Block: 256 threads = 8 warps, 128 edges/block, 16 edges/warp (2 tiles of 8).
// smem (floats): cv[128] | h1[128][132] | h2[128][260]   (padding -> conflict-free)
#define H1PAD 132
#define H2PAD 260
#define SM_CV 0
#define SM_H1 128
#define SM_H2 (128 + 128*H1PAD)
#define MLP_SMEMF (128 + 128*H1PAD + 128*H2PAD)

__global__ void __launch_bounds__(256,1)
k_mlp_mma(const float* __restrict__ attr, const float* __restrict__ ewt,
          const float* __restrict__ b1, const float* __restrict__ b2,
          const float* __restrict__ b3raw, int l){
    extern __shared__ float sm[];
    float* cv = sm + SM_CV;
    float* h1 = sm + SM_H1;
    float* h2 = sm + SM_H2;
    int tid = threadIdx.x;
    int warp = tid>>5, lane = tid&31;
    int g = lane>>2, t = lane&3;
    int eblk = blockIdx.x*128;
    int eloc0 = warp*16;

    const float2* W1 = (const float2*)g_W1hl + (size_t)l*4096;
    const float2* W2 = (const float2*)g_W2hl + (size_t)l*32768;
    const float2* W3 = (const float2*)g_W3hl + (size_t)l*98304;

    if(lane < 16){
        float wv = ewt[eblk + eloc0 + lane];
        cv[eloc0+lane] = (wv < CUT) ? 0.5f*(cosf(wv*(3.14159265358979f/CUT))+1.f) : 0.f;
    }
    __syncwarp();

    // ---- stage 1: [16e x 32] x W1^T -> h1[16e x 128] ----
    for(int ot=0; ot<8; ot++){
        int o0 = ot*16;
        float d[2][4];
        #pragma unroll
        for(int et=0;et<2;et++){ d[et][0]=d[et][1]=d[et][2]=d[et][3]=0.f; }
        for(int kc=0; kc<4; kc++){
            int k0 = kc*8;
            float2 A0 = W1[(o0+g)*32 + k0+t];
            float2 A1 = W1[(o0+g+8)*32 + k0+t];
            float2 A2 = W1[(o0+g)*32 + k0+t+4];
            float2 A3 = W1[(o0+g+8)*32 + k0+t+4];
            uint32_t ah[4] = {__float_as_uint(A0.x),__float_as_uint(A1.x),__float_as_uint(A2.x),__float_as_uint(A3.x)};
            uint32_t al[4] = {__float_as_uint(A0.y),__float_as_uint(A1.y),__float_as_uint(A2.y),__float_as_uint(A3.y)};
            #pragma unroll
            for(int et=0;et<2;et++){
                int eB = eblk + eloc0 + et*8 + g;
                float v0 = attr[(size_t)eB*32 + k0+t];
                float v1 = attr[(size_t)eB*32 + k0+t+4];
                uint32_t bh[2], bl[2];
                splitb(v0, bh[0], bl[0]); splitb(v1, bh[1], bl[1]);
                mma8(d[et], ah, bh); mma8(d[et], ah, bl); mma8(d[et], al, bh);
            }
        }
        float bA = b1[o0+g], bB = b1[o0+g+8];
        #pragma unroll
        for(int et=0;et<2;et++){
            int e = eloc0 + et*8 + 2*t;
            h1[e*H1PAD + o0+g]       = siluf(d[et][0]+bA);
            h1[(e+1)*H1PAD + o0+g]   = siluf(d[et][1]+bA);
            h1[e*H1PAD + o0+g+8]     = siluf(d[et][2]+bB);
            h1[(e+1)*H1PAD + o0+g+8] = siluf(d[et][3]+bB);
        }
    }
    __syncwarp();

    // ---- stage 2: [16e x 128] x W2^T -> h2[16e x 256] ----
    for(int ot=0; ot<16; ot++){
        int o0 = ot*16;
        float d[2][4];
        #pragma unroll
        for(int et=0;et<2;et++){ d[et][0]=d[et][1]=d[et][2]=d[et][3]=0.f; }
        for(int kc=0; kc<16; kc++){
            int k0 = kc*8;
            float2 A0 = W2[(o0+g)*128 + k0+t];
            float2 A1 = W2[(o0+g+8)*128 + k0+t];
            float2 A2 = W2[(o0+g)*128 + k0+t+4];
            float2 A3 = W2[(o0+g+8)*128 + k0+t+4];
            uint32_t ah[4] = {__float_as_uint(A0.x),__float_as_uint(A1.x),__float_as_uint(A2.x),__float_as_uint(A3.x)};
            uint32_t al[4] = {__float_as_uint(A0.y),__float_as_uint(A1.y),__float_as_uint(A2.y),__float_as_uint(A3.y)};
            #pragma unroll
            for(int et=0;et<2;et++){
                int eB = eloc0 + et*8 + g;
                float v0 = h1[eB*H1PAD + k0+t];
                float v1 = h1[eB*H1PAD + k0+t+4];
                uint32_t bh[2], bl[2];
                splitb(v0, bh[0], bl[0]); splitb(v1, bh[1], bl[1]);
                mma8(d[et], ah, bh); mma8(d[et], ah, bl); mma8(d[et], al, bh);
            }
        }
        float bA = b2[o0+g], bB = b2[o0+g+8];
        #pragma unroll
        for(int et=0;et<2;et++){
            int e = eloc0 + et*8 + 2*t;
            h2[e*H2PAD + o0+g]       = siluf(d[et][0]+bA);
            h2[(e+1)*H2PAD + o0+g]   = siluf(d[et][1]+bA);
            h2[e*H2PAD + o0+g+8]     = siluf(d[et][2]+bB);
            h2[(e+1)*H2PAD + o0+g+8] = siluf(d[et][3]+bB);
        }
    }
    __syncwarp();

    // ---- stage 3: [16e x 256] x W3'^T -> g_ea[e][o'] (o' = c*128+h) ----
    float* scr = h1 + warp*320;      // 16 x 20 per-warp scratch (h1 is dead now)
    for(int ot=0; ot<24; ot++){
        int o0 = ot*16;
        float d[2][4];
        #pragma unroll
        for(int et=0;et<2;et++){ d[et][0]=d[et][1]=d[et][2]=d[et][3]=0.f; }
        for(int kc=0; kc<32; kc++){
            int k0 = kc*8;
            float2 A0 = W3[(o0+g)*256 + k0+t];
            float2 A1 = W3[(o0+g+8)*256 + k0+t];
            float2 A2 = W3[(o0+g)*256 + k0+t+4];
            float2 A3 = W3[(o0+g+8)*256 + k0+t+4];
            uint32_t ah[4] = {__float_as_uint(A0.x),__float_as_uint(A1.x),__float_as_uint(A2.x),__float_as_uint(A3.x)};
            uint32_t al[4] = {__float_as_uint(A0.y),__float_as_uint(A1.y),__float_as_uint(A2.y),__float_as_uint(A3.y)};
            #pragma unroll
            for(int et=0;et<2;et++){
                int eB = eloc0 + et*8 + g;
                float v0 = h2[eB*H2PAD + k0+t];
                float v1 = h2[eB*H2PAD + k0+t+4];
                uint32_t bh[2], bl[2];
                splitb(v0, bh[0], bl[0]); splitb(v1, bh[1], bl[1]);
                mma8(d[et], ah, bh); mma8(d[et], ah, bl); mma8(d[et], al, bh);
            }
        }
        // bias (permuted index): original j = (o'&127)*3 + (o'>>7)
        int oA = o0+g, oB = o0+g+8;
        float bA = b3raw[(oA&127)*3 + (oA>>7)];
        float bB = b3raw[(oB&127)*3 + (oB>>7)];
        #pragma unroll
        for(int et=0;et<2;et++){
            int e = et*8 + 2*t;
            float c0 = cv[eloc0+e], c1 = cv[eloc0+e+1];
            scr[e*20 + g]       = siluf(d[et][0]+bA)*c0;
            scr[(e+1)*20 + g]   = siluf(d[et][1]+bA)*c1;
            scr[e*20 + g+8]     = siluf(d[et][2]+bB)*c0;
            scr[(e+1)*20 + g+8] = siluf(d[et][3]+bB)*c1;
        }
        __syncwarp();
        // coalesced copy-out: 16 edges x 16 channels = 64 float4 tokens
        #pragma unroll
        for(int tk=lane; tk<64; tk+=32){
            int e = tk>>2, qq = tk&3;
            float4 v = *(float4*)&scr[e*20 + qq*4];
            *(float4*)&g_ea[(size_t)(eblk+eloc0+e)*384 + o0 + qq*4] = v;
        }
        __syncwarp();
    }
}

// ---------------- gather segment-sum + O(3) node update ----------------
__global__ void __launch_bounds__(128) k_gather_update(const int* __restrict__ ei,
                                                       const float* __restrict__ q){
    int n = blockIdx.x;
    int h = threadIdx.x;
    int s = g_row[n], e1 = g_row[n+1];
    float cm[9];
    #pragma unroll
    for(int d=0;d<9;d++) cm[d]=0.f;
    for(int t=s;t<e1;t++){
        int e = g_eord[t];
        int dst = ei[NE + e];
        const float* ep = g_ea + (size_t)e*384;
        float a0=ep[h], a1=ep[128+h], a2=ep[256+h];
        int di = dst*HH + h;
        cm[0] += a0*g_cM[0*NH+di];
        cm[1] += a1*g_cM[1*NH+di];
        cm[2] += a1*g_cM[2*NH+di];
        cm[3] += a1*g_cM[3*NH+di];
        cm[4] += a2*g_cM[4*NH+di];
        cm[5] += a2*g_cM[5*NH+di];
        cm[6] += a2*g_cM[6*NH+di];
        cm[7] += a2*g_cM[7*NH+di];
        cm[8] += a2*g_cM[8*NH+di];
    }
    int idx = n*HH + h;
    float cy[9];
    #pragma unroll
    for(int d=0;d<9;d++) cy[d]=g_cM[d*NH+idx];
    float M[9], Y[9];
    rec(cm,M); rec(cy,Y);
    float AB[9];
    #pragma unroll
    for(int r=0;r<9;r++) AB[r]=0.f;
    mmadd(M,Y,AB); mmadd(Y,M,AB);
    float f = 1.f + 0.1f*q[n];
    float T[9]; float nrm=0.f;
    #pragma unroll
    for(int r=0;r<9;r++){ T[r]=f*AB[r]; nrm += T[r]*T[r]; }
    float inv = 1.f/(nrm+1.f);
    float c2[9]; tocompact(T,inv,c2);
    #pragma unroll
    for(int d=0;d<9;d++) g_c2[d*NH+idx]=c2[d];
}

// ---------------- final node update ----------------
__global__ void k_upd_b(const float* __restrict__ q, float* __restrict__ Xout){
    int idx = blockIdx.x*blockDim.x + threadIdx.x;
    if(idx>=NH) return;
    float c[9];
    #pragma unroll
    for(int d=0;d<9;d++) c[d]=g_dXc[d*NH+idx];
    float dx[9]; rec(c,dx);
    float f = 1.f + 0.1f*q[idx>>7];
    float D2[9];
    #pragma unroll
    for(int r=0;r<9;r++) D2[r]=0.f;
    mmadd(dx,dx,D2);
    #pragma unroll
    for(int r=0;r<9;r++)
        Xout[(size_t)idx*9+r] = g_Xn[(size_t)idx*9+r] + dx[r] + f*D2[r];
}

// ---------------- launcher ----------------
extern "C" void kernel_launch(void* const* d_in, const int* in_sizes, int n_in,
                              void* d_out, int out_size){
    const float* X    = (const float*)d_in[0];
    const float* attr = (const float*)d_in[1];
    const float* ewt  = (const float*)d_in[2];
    const float* q    = (const float*)d_in[3];
    const float* Ws1  = (const float*)d_in[4];
    const float* bs1  = (const float*)d_in[5];
    const float* Ws2  = (const float*)d_in[6];
    const float* bs2  = (const float*)d_in[7];
    const float* Ws3  = (const float*)d_in[8];
    const float* bs3  = (const float*)d_in[9];
    const float* Wt   = (const float*)d_in[10];
    const int*   ei   = (const int*)d_in[11];
    float* out = (float*)d_out;

    cudaFuncSetAttribute(k_mlp_mma, cudaFuncAttributeMaxDynamicSharedMemorySize,
                         MLP_SMEMF*4);

    k_prep_w<<<264,256>>>(Ws1,Ws2,Ws3,Wt);
    k_zero_cnt<<<(NA+255)/256,256>>>();
    k_count<<<NE/256,256>>>(ei);
    k_scan<<<1,1024>>>();
    k_place<<<NE/256,256>>>(ei);

    for(int l=0;l<2;l++){
        k_node_prep<<<NH/256,256>>>(l==0 ? X : out);
        k_mix<<<dim3(64,9),128>>>(0, l*6);
        k_mlp_mma<<<NE/128,256,MLP_SMEMF*4>>>(attr, ewt, bs1+l*128, bs2+l*256, bs3+l*384, l);
        k_gather_update<<<NA,128>>>(ei, q);
        k_mix<<<dim3(64,9),128>>>(1, l*6+3);
        k_upd_b<<<NH/256,256>>>(q, out);
    }
}

// round 5
// speedup vs baseline: 1.5736x; 1.5736x over previous
#include <cuda_runtime.h>
#include <cstdint>
#include <cstddef>

#define NA 2048
#define HH 128
#define NE 32768
#define RR 32
#define NH (NA*HH)
#define CUT 4.5f

// ---------------- scratch (static device globals; no allocations) ----------------
__device__ float g_ea[NE*384];      // edge MLP output, layout [e][3][128]
__device__ float g_Xn[NH*9];        // normalized X
__device__ float g_cA[9*NH];        // compact planes of Xn (pre-mix)
__device__ float g_cM[9*NH];        // compact planes after chan_mix
__device__ float g_c2[9*NH];        // compact planes of scaled/normalized AB
__device__ float g_dXc[9*NH];       // compact planes of dX
__device__ float g_W1hl[2*128*32*2];    // [l][o][k]{hi,lo}
__device__ float g_W2hl[2*256*128*2];   // [l][o][k]{hi,lo}
__device__ float g_W3hl[2*384*256*2];   // [l][o'][k]{hi,lo}, o' = c*128+h
__device__ float g_WtT[12*HH*HH];       // [l*6+m][h][g]
__device__ int   g_cnt[NA];
__device__ int   g_cur[NA];
__device__ int   g_row[NA+1];
__device__ int   g_eord[NE];

typedef unsigned long long u64;

// ---------------- generic helpers ----------------
__device__ __forceinline__ u64 pk(float a, float b){
    u64 r; asm("mov.b64 %0, {%1,%2};" : "=l"(r) : "f"(a), "f"(b)); return r;
}
__device__ __forceinline__ void upk(u64 v, float& a, float& b){
    asm("mov.b64 {%0,%1}, %2;" : "=f"(a), "=f"(b) : "l"(v));
}
__device__ __forceinline__ void fma2(u64& d, u64 a, u64 b){
    asm("fma.rn.f32x2 %0, %1, %2, %0;" : "+l"(d) : "l"(a), "l"(b));
}
__device__ __forceinline__ float siluf(float x){ return x / (1.f + __expf(-x)); }
__device__ __forceinline__ float tf32r(float x){
    uint32_t u; asm("cvt.rna.tf32.f32 %0, %1;" : "=r"(u) : "f"(x));
    return __uint_as_float(u);
}

// m16n8k8 tf32 mma: D(16x8) += A(16x8,row) * B(8x8,col)
__device__ __forceinline__ void mma8(float* d, const uint32_t* a, const uint32_t* b){
    asm volatile("mma.sync.aligned.m16n8k8.row.col.f32.tf32.tf32.f32 "
        "{%0,%1,%2,%3}, {%4,%5,%6,%7}, {%8,%9}, {%0,%1,%2,%3};"
        : "+f"(d[0]),"+f"(d[1]),"+f"(d[2]),"+f"(d[3])
        : "r"(a[0]),"r"(a[1]),"r"(a[2]),"r"(a[3]), "r"(b[0]),"r"(b[1]));
}

// split an fp32 value into two canonical-tf32 parts (hi via mantissa truncation)
__device__ __forceinline__ void splitb(float v, uint32_t& h, uint32_t& lo){
    uint32_t u = __float_as_uint(v);
    h = u & 0xFFFFE000u;
    float r = v - __uint_as_float(h);
    lo = __float_as_uint(r) & 0xFFFFE000u;
}

// compact basis: {i0, a01, a02, a12, s00, s01, s02, s11, s12}
__device__ __forceinline__ void tocompact(const float* t, float s, float* c){
    float i0 = (t[0]+t[4]+t[8])*(1.f/3.f);
    c[0] = i0*s;
    c[1] = 0.5f*(t[1]-t[3])*s;
    c[2] = 0.5f*(t[2]-t[6])*s;
    c[3] = 0.5f*(t[5]-t[7])*s;
    c[4] = (t[0]-i0)*s;
    c[5] = 0.5f*(t[1]+t[3])*s;
    c[6] = 0.5f*(t[2]+t[6])*s;
    c[7] = (t[4]-i0)*s;
    c[8] = 0.5f*(t[5]+t[7])*s;
}
__device__ __forceinline__ void rec(const float* c, float* t){
    float i0=c[0], a01=c[1], a02=c[2], a12=c[3];
    float s00=c[4], s01=c[5], s02=c[6], s11=c[7], s12=c[8];
    t[0]=i0+s00;  t[1]=a01+s01; t[2]=a02+s02;
    t[3]=s01-a01; t[4]=i0+s11;  t[5]=a12+s12;
    t[6]=s02-a02; t[7]=s12-a12; t[8]=i0-s00-s11;
}
__device__ __forceinline__ void mmadd(const float* A, const float* B, float* C){
    #pragma unroll
    for(int i=0;i<3;i++){
        #pragma unroll
        for(int j=0;j<3;j++)
            C[i*3+j] += A[i*3+0]*B[0*3+j] + A[i*3+1]*B[1*3+j] + A[i*3+2]*B[2*3+j];
    }
}

// ---------------- weight prep: hi/lo tf32 splits + WtT transpose ----------------
__global__ void k_prep_w(const float* __restrict__ Ws1, const float* __restrict__ Ws2,
                         const float* __restrict__ Ws3, const float* __restrict__ Wt){
    int stride = gridDim.x*blockDim.x;
    int t0 = blockIdx.x*blockDim.x + threadIdx.x;
    for(int i=t0;i<2*128*32;i+=stride){
        float w = Ws1[i]; float hi = tf32r(w);
        g_W1hl[i*2]=hi; g_W1hl[i*2+1]=tf32r(w-hi);
    }
    for(int i=t0;i<2*256*128;i+=stride){
        float w = Ws2[i]; float hi = tf32r(w);
        g_W2hl[i*2]=hi; g_W2hl[i*2+1]=tf32r(w-hi);
    }
    // W3 with output-row permutation: src row j = h*3+c  ->  dst row o' = c*128+h
    for(int i=t0;i<2*384*256;i+=stride){
        int l=i/98304, r=i%98304, j=r/256, k=r%256;
        int op = (j%3)*128 + j/3;
        float w = Ws3[i]; float hi = tf32r(w);
        int di = (l*98304 + op*256 + k)*2;
        g_W3hl[di]=hi; g_W3hl[di+1]=tf32r(w-hi);
    }
    for(int i=t0;i<12*128*128;i+=stride){
        int lm=i/16384, r=i%16384, g=r/128, hh=r%128;
        g_WtT[lm*16384 + hh*128 + g] = Wt[i];
    }
}

// ---------------- CSR build ----------------
__global__ void k_zero_cnt(){
    int i = blockIdx.x*blockDim.x + threadIdx.x;
    if(i<NA){ g_cnt[i]=0; g_cur[i]=0; }
}
__global__ void k_count(const int* __restrict__ ei){
    int e = blockIdx.x*blockDim.x + threadIdx.x;
    if(e<NE) atomicAdd(&g_cnt[ei[e]], 1);
}
__global__ void k_scan(){
    __shared__ int sh[1024];
    int t = threadIdx.x;
    int v0 = g_cnt[2*t], v1 = g_cnt[2*t+1];
    int s = v0+v1;
    sh[t]=s; __syncthreads();
    #pragma unroll
    for(int off=1; off<1024; off<<=1){
        int x = (t>=off)? sh[t-off] : 0;
        __syncthreads();
        sh[t] += x;
        __syncthreads();
    }
    int incl = sh[t];
    int excl = incl - s;
    g_row[2*t]   = excl;
    g_row[2*t+1] = excl + v0;
    if(t==1023) g_row[2048]=incl;
}
__global__ void k_place(const int* __restrict__ ei){
    int e = blockIdx.x*blockDim.x + threadIdx.x;
    if(e<NE){
        int s = ei[e];
        int p = atomicAdd(&g_cur[s],1);
        g_eord[g_row[s]+p] = e;
    }
}

// ---------------- node prep: normalize + compact decompose ----------------
__global__ void k_node_prep(const float* __restrict__ Xin){
    int idx = blockIdx.x*blockDim.x + threadIdx.x;
    if(idx>=NH) return;
    float t[9]; float nrm=0.f;
    #pragma unroll
    for(int r=0;r<9;r++){ t[r]=Xin[(size_t)idx*9+r]; nrm += t[r]*t[r]; }
    float inv = 1.f/(nrm+1.f);
    #pragma unroll
    for(int r=0;r<9;r++){ t[r]*=inv; g_Xn[(size_t)idx*9+r]=t[r]; }
    float c[9]; tocompact(t,1.f,c);
    #pragma unroll
    for(int d=0;d<9;d++) g_cA[d*NH+idx]=c[d];
}

// ---------------- channel mix (f32x2) ----------------
__global__ void __launch_bounds__(128) k_mix(int which, int wbase){
    __shared__ float sin_[32*128];
    const float* in  = which ? g_c2  : g_cA;
    float*       out = which ? g_dXc : g_cM;
    int d = blockIdx.y;
    int m = (d==0)?0:((d<4)?1:2);
    const float* W = g_WtT + (size_t)(wbase+m)*16384;
    int n0 = blockIdx.x*32;
    const float* src = in + (size_t)d*NH + (size_t)n0*HH;
    for(int i=threadIdx.x;i<1024;i+=128)
        ((float4*)sin_)[i] = ((const float4*)src)[i];
    __syncthreads();
    int w = threadIdx.x>>5, lane = threadIdx.x&31;
    u64 acc[8][2];
    #pragma unroll
    for(int i=0;i<8;i++){ acc[i][0]=0ull; acc[i][1]=0ull; }
    for(int k=0;k<128;k++){
        float4 wf = *(const float4*)&W[k*128 + lane*4];
        u64 w0=pk(wf.x,wf.y), w1=pk(wf.z,wf.w);
        #pragma unroll
        for(int i=0;i<8;i++){
            float v = sin_[(w*8+i)*128 + k];
            u64 vp = pk(v,v);
            fma2(acc[i][0],vp,w0); fma2(acc[i][1],vp,w1);
        }
    }
    float* dst = out + (size_t)d*NH + (size_t)n0*HH;
    #pragma unroll
    for(int i=0;i<8;i++){
        float4 o; upk(acc[i][0],o.x,o.y); upk(acc[i][1],o.z,o.w);
        *(float4*)&dst[(w*8+i)*HH + lane*4] = o;
    }
}

// ---------------- edge MLP via mma.sync tf32 (hi/lo), warps partition OUTPUTS ----
// Block: 256 threads = 8 warps, 128 edges/block.
// A = weights (warp-private output slice, from global), B = activations (smem).
// smem floats: cv[128] | h1[128][132] | h2[128][260]; attr aliases h2 (stage1 only).
#define H1PAD 132
#define H2PAD 260
#define MLP_SMEMF (128 + 128*H1PAD + 128*H2PAD)

__global__ void __launch_bounds__(256,1)
k_mlp_mma(const float* __restrict__ attr, const float* __restrict__ ewt,
          const float* __restrict__ b1, const float* __restrict__ b2,
          const float* __restrict__ b3raw, int l){
    extern __shared__ float sm[];
    float* cv = sm;
    float* h1 = sm + 128;
    float* h2 = sm + 128 + 128*H1PAD;
    float* s_attr = h2;               // alias: 128 x 36, stage-1 input only
    int tid = threadIdx.x;
    int warp = tid>>5, lane = tid&31;
    int g = lane>>2, t = lane&3;
    int eblk = blockIdx.x*128;

    const float2* W1 = (const float2*)g_W1hl + (size_t)l*4096;
    const float2* W2 = (const float2*)g_W2hl + (size_t)l*32768;
    const float2* W3 = (const float2*)g_W3hl + (size_t)l*98304;

    // stage attr into smem (pad 36 -> conflict-free (4g+t) fragment reads)
    for(int i=tid;i<1024;i+=256){
        int e=i>>3, k4=(i&7)<<2;
        float4 v = *(const float4*)&attr[(size_t)(eblk+e)*32 + k4];
        *(float4*)&s_attr[e*36 + k4] = v;
    }
    if(tid<128){
        float wv = ewt[eblk+tid];
        cv[tid] = (wv < CUT) ? 0.5f*(cosf(wv*(3.14159265358979f/CUT))+1.f) : 0.f;
    }
    __syncthreads();

    // ---- stage 1: outputs [16w,16w+16), all 128 edges (16 edge-tiles) ----
    {
        float d[16][4];
        #pragma unroll
        for(int nt=0;nt<16;nt++){ d[nt][0]=d[nt][1]=d[nt][2]=d[nt][3]=0.f; }
        int o = warp*16;
        #pragma unroll
        for(int kc=0;kc<4;kc++){
            int k0=kc*8;
            float2 A0=W1[(o+g)*32+k0+t],   A1=W1[(o+g+8)*32+k0+t];
            float2 A2=W1[(o+g)*32+k0+t+4], A3=W1[(o+g+8)*32+k0+t+4];
            uint32_t ah[4]={__float_as_uint(A0.x),__float_as_uint(A1.x),__float_as_uint(A2.x),__float_as_uint(A3.x)};
            uint32_t al[4]={__float_as_uint(A0.y),__float_as_uint(A1.y),__float_as_uint(A2.y),__float_as_uint(A3.y)};
            #pragma unroll
            for(int nt=0;nt<16;nt++){
                int e = nt*8+g;
                float v0 = s_attr[e*36+k0+t], v1 = s_attr[e*36+k0+t+4];
                uint32_t bh[2], bl[2];
                splitb(v0,bh[0],bl[0]); splitb(v1,bh[1],bl[1]);
                mma8(d[nt],ah,bh); mma8(d[nt],ah,bl); mma8(d[nt],al,bh);
            }
        }
        float bA=b1[o+g], bB=b1[o+g+8];
        #pragma unroll
        for(int nt=0;nt<16;nt++){
            int e = nt*8 + 2*t;
            h1[e*H1PAD + o+g]       = siluf(d[nt][0]+bA);
            h1[(e+1)*H1PAD + o+g]   = siluf(d[nt][1]+bA);
            h1[e*H1PAD + o+g+8]     = siluf(d[nt][2]+bB);
            h1[(e+1)*H1PAD + o+g+8] = siluf(d[nt][3]+bB);
        }
    }
    __syncthreads();

    // ---- stage 2: outputs [32w,32w+32) (2 m-tiles), K=128, edge halves of 64 ----
    #pragma unroll 1
    for(int half=0; half<2; half++){
        float d[2][8][4];
        #pragma unroll
        for(int m=0;m<2;m++)
            #pragma unroll
            for(int nt=0;nt<8;nt++){ d[m][nt][0]=d[m][nt][1]=d[m][nt][2]=d[m][nt][3]=0.f; }
        #pragma unroll 1
        for(int kc=0;kc<16;kc++){
            int k0=kc*8;
            uint32_t ah[2][4], al[2][4];
            #pragma unroll
            for(int m=0;m<2;m++){
                int o = warp*32 + m*16;
                float2 A0=W2[(o+g)*128+k0+t],   A1=W2[(o+g+8)*128+k0+t];
                float2 A2=W2[(o+g)*128+k0+t+4], A3=W2[(o+g+8)*128+k0+t+4];
                ah[m][0]=__float_as_uint(A0.x); ah[m][1]=__float_as_uint(A1.x);
                ah[m][2]=__float_as_uint(A2.x); ah[m][3]=__float_as_uint(A3.x);
                al[m][0]=__float_as_uint(A0.y); al[m][1]=__float_as_uint(A1.y);
                al[m][2]=__float_as_uint(A2.y); al[m][3]=__float_as_uint(A3.y);
            }
            #pragma unroll
            for(int nt=0;nt<8;nt++){
                int e = half*64 + nt*8 + g;
                float v0 = h1[e*H1PAD+k0+t], v1 = h1[e*H1PAD+k0+t+4];
                uint32_t bh[2], bl[2];
                splitb(v0,bh[0],bl[0]); splitb(v1,bh[1],bl[1]);
                #pragma unroll
                for(int m=0;m<2;m++){
                    mma8(d[m][nt],ah[m],bh); mma8(d[m][nt],ah[m],bl); mma8(d[m][nt],al[m],bh);
                }
            }
        }
        #pragma unroll
        for(int m=0;m<2;m++){
            int o = warp*32 + m*16;
            float bA=b2[o+g], bB=b2[o+g+8];
            #pragma unroll
            for(int nt=0;nt<8;nt++){
                int e = half*64 + nt*8 + 2*t;
                h2[e*H2PAD + o+g]       = siluf(d[m][nt][0]+bA);
                h2[(e+1)*H2PAD + o+g]   = siluf(d[m][nt][1]+bA);
                h2[e*H2PAD + o+g+8]     = siluf(d[m][nt][2]+bB);
                h2[(e+1)*H2PAD + o+g+8] = siluf(d[m][nt][3]+bB);
            }
        }
    }
    __syncthreads();

    // ---- stage 3: outputs [48w,48w+48) (3 m-tiles), K=256, edge halves of 64 ----
    #pragma unroll 1
    for(int half=0; half<2; half++){
        float d[3][8][4];
        #pragma unroll
        for(int m=0;m<3;m++)
            #pragma unroll
            for(int nt=0;nt<8;nt++){ d[m][nt][0]=d[m][nt][1]=d[m][nt][2]=d[m][nt][3]=0.f; }
        #pragma unroll 1
        for(int kc=0;kc<32;kc++){
            int k0=kc*8;
            uint32_t ah[3][4], al[3][4];
            #pragma unroll
            for(int m=0;m<3;m++){
                int o = warp*48 + m*16;
                float2 A0=W3[(o+g)*256+k0+t],   A1=W3[(o+g+8)*256+k0+t];
                float2 A2=W3[(o+g)*256+k0+t+4], A3=W3[(o+g+8)*256+k0+t+4];
                ah[m][0]=__float_as_uint(A0.x); ah[m][1]=__float_as_uint(A1.x);
                ah[m][2]=__float_as_uint(A2.x); ah[m][3]=__float_as_uint(A3.x);
                al[m][0]=__float_as_uint(A0.y); al[m][1]=__float_as_uint(A1.y);
                al[m][2]=__float_as_uint(A2.y); al[m][3]=__float_as_uint(A3.y);
            }
            #pragma unroll
            for(int nt=0;nt<8;nt++){
                int e = half*64 + nt*8 + g;
                float v0 = h2[e*H2PAD+k0+t], v1 = h2[e*H2PAD+k0+t+4];
                uint32_t bh[2], bl[2];
                splitb(v0,bh[0],bl[0]); splitb(v1,bh[1],bl[1]);
                #pragma unroll
                for(int m=0;m<3;m++){
                    mma8(d[m][nt],ah[m],bh); mma8(d[m][nt],ah[m],bl); mma8(d[m][nt],al[m],bh);
                }
            }
        }
        #pragma unroll
        for(int m=0;m<3;m++){
            int oA = warp*48 + m*16 + g, oB = oA + 8;
            float bA = b3raw[(oA&127)*3 + (oA>>7)];
            float bB = b3raw[(oB&127)*3 + (oB>>7)];
            #pragma unroll
            for(int nt=0;nt<8;nt++){
                int e0 = half*64 + nt*8 + 2*t;
                float c0 = cv[e0], c1 = cv[e0+1];
                float* ep0 = g_ea + (size_t)(eblk+e0)*384;
                float* ep1 = g_ea + (size_t)(eblk+e0+1)*384;
                ep0[oA] = siluf(d[m][nt][0]+bA)*c0;
                ep1[oA] = siluf(d[m][nt][1]+bA)*c1;
                ep0[oB] = siluf(d[m][nt][2]+bB)*c0;
                ep1[oB] = siluf(d[m][nt][3]+bB)*c1;
            }
        }
    }
}

// ---------------- gather segment-sum + O(3) node update ----------------
__global__ void __launch_bounds__(128) k_gather_update(const int* __restrict__ ei,
                                                       const float* __restrict__ q){
    int n = blockIdx.x;
    int h = threadIdx.x;
    int s = g_row[n], e1 = g_row[n+1];
    float cm[9];
    #pragma unroll
    for(int d=0;d<9;d++) cm[d]=0.f;
    for(int t=s;t<e1;t++){
        int e = g_eord[t];
        int dst = ei[NE + e];
        const float* ep = g_ea + (size_t)e*384;
        float a0=ep[h], a1=ep[128+h], a2=ep[256+h];
        int di = dst*HH + h;
        cm[0] += a0*g_cM[0*NH+di];
        cm[1] += a1*g_cM[1*NH+di];
        cm[2] += a1*g_cM[2*NH+di];
        cm[3] += a1*g_cM[3*NH+di];
        cm[4] += a2*g_cM[4*NH+di];
        cm[5] += a2*g_cM[5*NH+di];
        cm[6] += a2*g_cM[6*NH+di];
        cm[7] += a2*g_cM[7*NH+di];
        cm[8] += a2*g_cM[8*NH+di];
    }
    int idx = n*HH + h;
    float cy[9];
    #pragma unroll
    for(int d=0;d<9;d++) cy[d]=g_cM[d*NH+idx];
    float M[9], Y[9];
    rec(cm,M); rec(cy,Y);
    float AB[9];
    #pragma unroll
    for(int r=0;r<9;r++) AB[r]=0.f;
    mmadd(M,Y,AB); mmadd(Y,M,AB);
    float f = 1.f + 0.1f*q[n];
    float T[9]; float nrm=0.f;
    #pragma unroll
    for(int r=0;r<9;r++){ T[r]=f*AB[r]; nrm += T[r]*T[r]; }
    float inv = 1.f/(nrm+1.f);
    float c2[9]; tocompact(T,inv,c2);
    #pragma unroll
    for(int d=0;d<9;d++) g_c2[d*NH+idx]=c2[d];
}

// ---------------- final node update ----------------
__global__ void k_upd_b(const float* __restrict__ q, float* __restrict__ Xout){
    int idx = blockIdx.x*blockDim.x + threadIdx.x;
    if(idx>=NH) return;
    float c[9];
    #pragma unroll
    for(int d=0;d<9;d++) c[d]=g_dXc[d*NH+idx];
    float dx[9]; rec(c,dx);
    float f = 1.f + 0.1f*q[idx>>7];
    float D2[9];
    #pragma unroll
    for(int r=0;r<9;r++) D2[r]=0.f;
    mmadd(dx,dx,D2);
    #pragma unroll
    for(int r=0;r<9;r++)
        Xout[(size_t)idx*9+r] = g_Xn[(size_t)idx*9+r] + dx[r] + f*D2[r];
}

// ---------------- launcher ----------------
extern "C" void kernel_launch(void* const* d_in, const int* in_sizes, int n_in,
                              void* d_out, int out_size){
    const float* X    = (const float*)d_in[0];
    const float* attr = (const float*)d_in[1];
    const float* ewt  = (const float*)d_in[2];
    const float* q    = (const float*)d_in[3];
    const float* Ws1  = (const float*)d_in[4];
    const float* bs1  = (const float*)d_in[5];
    const float* Ws2  = (const float*)d_in[6];
    const float* bs2  = (const float*)d_in[7];
    const float* Ws3  = (const float*)d_in[8];
    const float* bs3  = (const float*)d_in[9];
    const float* Wt   = (const float*)d_in[10];
    const int*   ei   = (const int*)d_in[11];
    float* out = (float*)d_out;

    cudaFuncSetAttribute(k_mlp_mma, cudaFuncAttributeMaxDynamicSharedMemorySize,
                         MLP_SMEMF*4);

    k_prep_w<<<264,256>>>(Ws1,Ws2,Ws3,Wt);
    k_zero_cnt<<<(NA+255)/256,256>>>();
    k_count<<<NE/256,256>>>(ei);
    k_scan<<<1,1024>>>();
    k_place<<<NE/256,256>>>(ei);

    for(int l=0;l<2;l++){
        k_node_prep<<<NH/256,256>>>(l==0 ? X : out);
        k_mix<<<dim3(64,9),128>>>(0, l*6);
        k_mlp_mma<<<NE/128,256,MLP_SMEMF*4>>>(attr, ewt, bs1+l*128, bs2+l*256, bs3+l*384, l);
        k_gather_update<<<NA,128>>>(ei, q);
        k_mix<<<dim3(64,9),128>>>(1, l*6+3);
        k_upd_b<<<NH/256,256>>>(q, out);
    }
}

// round 6
// speedup vs baseline: 1.5885x; 1.0094x over previous
#include <cuda_runtime.h>
#include <cstdint>
#include <cstddef>

#define NA 2048
#define HH 128
#define NE 32768
#define RR 32
#define NH (NA*HH)
#define CUT 4.5f

// ---------------- scratch (static device globals; no allocations) ----------------
__device__ float g_ea[NE*384];      // edge MLP output, layout [e][3][128]
__device__ float g_Xn[NH*9];        // normalized X
__device__ float g_cA[9*NH];        // compact planes of Xn (pre-mix)
__device__ float g_cM[9*NH];        // compact planes after chan_mix
__device__ float g_c2[9*NH];        // compact planes of scaled/normalized AB
__device__ float g_dXc[9*NH];       // compact planes of dX
__device__ float g_W1hl[2*128*32*2];    // [l][o][k]{hi,lo}
__device__ float g_W2hl[2*256*128*2];   // [l][o][k]{hi,lo}
__device__ float g_W3hl[2*384*256*2];   // [l][o'][k]{hi,lo}, o' = c*128+h
__device__ float g_WtT[12*HH*HH];       // [l*6+m][h][g]
__device__ int   g_cnt[NA];
__device__ int   g_cur[NA];
__device__ int   g_row[NA+1];
__device__ int   g_eord[NE];

typedef unsigned long long u64;

// ---------------- generic helpers ----------------
__device__ __forceinline__ u64 pk(float a, float b){
    u64 r; asm("mov.b64 %0, {%1,%2};" : "=l"(r) : "f"(a), "f"(b)); return r;
}
__device__ __forceinline__ void upk(u64 v, float& a, float& b){
    asm("mov.b64 {%0,%1}, %2;" : "=f"(a), "=f"(b) : "l"(v));
}
__device__ __forceinline__ void fma2(u64& d, u64 a, u64 b){
    asm("fma.rn.f32x2 %0, %1, %2, %0;" : "+l"(d) : "l"(a), "l"(b));
}
__device__ __forceinline__ float siluf(float x){ return x / (1.f + __expf(-x)); }
__device__ __forceinline__ float tf32r(float x){
    uint32_t u; asm("cvt.rna.tf32.f32 %0, %1;" : "=r"(u) : "f"(x));
    return __uint_as_float(u);
}

// m16n8k8 tf32 mma: D(16x8) += A(16x8,row) * B(8x8,col)
__device__ __forceinline__ void mma8(float* d, const uint32_t* a, const uint32_t* b){
    asm volatile("mma.sync.aligned.m16n8k8.row.col.f32.tf32.tf32.f32 "
        "{%0,%1,%2,%3}, {%4,%5,%6,%7}, {%8,%9}, {%0,%1,%2,%3};"
        : "+f"(d[0]),"+f"(d[1]),"+f"(d[2]),"+f"(d[3])
        : "r"(a[0]),"r"(a[1]),"r"(a[2]),"r"(a[3]), "r"(b[0]),"r"(b[1]));
}

// split an fp32 value into two canonical-tf32 parts (hi via mantissa truncation)
__device__ __forceinline__ void splitb(float v, uint32_t& h, uint32_t& lo){
    uint32_t u = __float_as_uint(v);
    h = u & 0xFFFFE000u;
    float r = v - __uint_as_float(h);
    lo = __float_as_uint(r) & 0xFFFFE000u;
}

// weight fragment load: 4 float2 (hi,lo) for one 16-row m-tile at k-chunk k0
__device__ __forceinline__ void ldw(const float2* __restrict__ W, int stride, int o,
                                    int k0, int g, int t, float2 (&buf)[4]){
    buf[0]=W[(o+g)*stride + k0+t];
    buf[1]=W[(o+g+8)*stride + k0+t];
    buf[2]=W[(o+g)*stride + k0+t+4];
    buf[3]=W[(o+g+8)*stride + k0+t+4];
}

// MMA block for one k-chunk over M m-tiles x 8 edge-tiles (hi/lo compensated)
template<int M>
__device__ __forceinline__ void do_mma(float (&d)[M][8][4], const float2 (&wb)[M][4],
                                       const float* __restrict__ act, int pad,
                                       int ebase, int k0, int g, int t){
    uint32_t ah[M][4], al[M][4];
    #pragma unroll
    for(int m=0;m<M;m++)
        #pragma unroll
        for(int j=0;j<4;j++){
            ah[m][j]=__float_as_uint(wb[m][j].x);
            al[m][j]=__float_as_uint(wb[m][j].y);
        }
    #pragma unroll
    for(int nt=0;nt<8;nt++){
        int e = ebase + nt*8 + g;
        float v0 = act[e*pad + k0+t], v1 = act[e*pad + k0+t+4];
        uint32_t bh[2], bl[2];
        splitb(v0,bh[0],bl[0]); splitb(v1,bh[1],bl[1]);
        #pragma unroll
        for(int m=0;m<M;m++){
            mma8(d[m][nt],ah[m],bh); mma8(d[m][nt],ah[m],bl); mma8(d[m][nt],al[m],bh);
        }
    }
}

// compact basis: {i0, a01, a02, a12, s00, s01, s02, s11, s12}
__device__ __forceinline__ void tocompact(const float* t, float s, float* c){
    float i0 = (t[0]+t[4]+t[8])*(1.f/3.f);
    c[0] = i0*s;
    c[1] = 0.5f*(t[1]-t[3])*s;
    c[2] = 0.5f*(t[2]-t[6])*s;
    c[3] = 0.5f*(t[5]-t[7])*s;
    c[4] = (t[0]-i0)*s;
    c[5] = 0.5f*(t[1]+t[3])*s;
    c[6] = 0.5f*(t[2]+t[6])*s;
    c[7] = (t[4]-i0)*s;
    c[8] = 0.5f*(t[5]+t[7])*s;
}
__device__ __forceinline__ void rec(const float* c, float* t){
    float i0=c[0], a01=c[1], a02=c[2], a12=c[3];
    float s00=c[4], s01=c[5], s02=c[6], s11=c[7], s12=c[8];
    t[0]=i0+s00;  t[1]=a01+s01; t[2]=a02+s02;
    t[3]=s01-a01; t[4]=i0+s11;  t[5]=a12+s12;
    t[6]=s02-a02; t[7]=s12-a12; t[8]=i0-s00-s11;
}
__device__ __forceinline__ void mmadd(const float* A, const float* B, float* C){
    #pragma unroll
    for(int i=0;i<3;i++){
        #pragma unroll
        for(int j=0;j<3;j++)
            C[i*3+j] += A[i*3+0]*B[0*3+j] + A[i*3+1]*B[1*3+j] + A[i*3+2]*B[2*3+j];
    }
}

// ---------------- weight prep: hi/lo tf32 splits + WtT transpose ----------------
__global__ void k_prep_w(const float* __restrict__ Ws1, const float* __restrict__ Ws2,
                         const float* __restrict__ Ws3, const float* __restrict__ Wt){
    int stride = gridDim.x*blockDim.x;
    int t0 = blockIdx.x*blockDim.x + threadIdx.x;
    for(int i=t0;i<2*128*32;i+=stride){
        float w = Ws1[i]; float hi = tf32r(w);
        g_W1hl[i*2]=hi; g_W1hl[i*2+1]=tf32r(w-hi);
    }
    for(int i=t0;i<2*256*128;i+=stride){
        float w = Ws2[i]; float hi = tf32r(w);
        g_W2hl[i*2]=hi; g_W2hl[i*2+1]=tf32r(w-hi);
    }
    // W3 with output-row permutation: src row j = h*3+c  ->  dst row o' = c*128+h
    for(int i=t0;i<2*384*256;i+=stride){
        int l=i/98304, r=i%98304, j=r/256, k=r%256;
        int op = (j%3)*128 + j/3;
        float w = Ws3[i]; float hi = tf32r(w);
        int di = (l*98304 + op*256 + k)*2;
        g_W3hl[di]=hi; g_W3hl[di+1]=tf32r(w-hi);
    }
    for(int i=t0;i<12*128*128;i+=stride){
        int lm=i/16384, r=i%16384, g=r/128, hh=r%128;
        g_WtT[lm*16384 + hh*128 + g] = Wt[i];
    }
}

// ---------------- CSR build ----------------
__global__ void k_zero_cnt(){
    int i = blockIdx.x*blockDim.x + threadIdx.x;
    if(i<NA){ g_cnt[i]=0; g_cur[i]=0; }
}
__global__ void k_count(const int* __restrict__ ei){
    int e = blockIdx.x*blockDim.x + threadIdx.x;
    if(e<NE) atomicAdd(&g_cnt[ei[e]], 1);
}
__global__ void k_scan(){
    __shared__ int sh[1024];
    int t = threadIdx.x;
    int v0 = g_cnt[2*t], v1 = g_cnt[2*t+1];
    int s = v0+v1;
    sh[t]=s; __syncthreads();
    #pragma unroll
    for(int off=1; off<1024; off<<=1){
        int x = (t>=off)? sh[t-off] : 0;
        __syncthreads();
        sh[t] += x;
        __syncthreads();
    }
    int incl = sh[t];
    int excl = incl - s;
    g_row[2*t]   = excl;
    g_row[2*t+1] = excl + v0;
    if(t==1023) g_row[2048]=incl;
}
__global__ void k_place(const int* __restrict__ ei){
    int e = blockIdx.x*blockDim.x + threadIdx.x;
    if(e<NE){
        int s = ei[e];
        int p = atomicAdd(&g_cur[s],1);
        g_eord[g_row[s]+p] = e;
    }
}

// ---------------- node prep: normalize + compact decompose ----------------
__global__ void k_node_prep(const float* __restrict__ Xin){
    int idx = blockIdx.x*blockDim.x + threadIdx.x;
    if(idx>=NH) return;
    float t[9]; float nrm=0.f;
    #pragma unroll
    for(int r=0;r<9;r++){ t[r]=Xin[(size_t)idx*9+r]; nrm += t[r]*t[r]; }
    float inv = 1.f/(nrm+1.f);
    #pragma unroll
    for(int r=0;r<9;r++){ t[r]*=inv; g_Xn[(size_t)idx*9+r]=t[r]; }
    float c[9]; tocompact(t,1.f,c);
    #pragma unroll
    for(int d=0;d<9;d++) g_cA[d*NH+idx]=c[d];
}

// ---------------- channel mix (f32x2) ----------------
__global__ void __launch_bounds__(128) k_mix(int which, int wbase){
    __shared__ float sin_[32*128];
    const float* in  = which ? g_c2  : g_cA;
    float*       out = which ? g_dXc : g_cM;
    int d = blockIdx.y;
    int m = (d==0)?0:((d<4)?1:2);
    const float* W = g_WtT + (size_t)(wbase+m)*16384;
    int n0 = blockIdx.x*32;
    const float* src = in + (size_t)d*NH + (size_t)n0*HH;
    for(int i=threadIdx.x;i<1024;i+=128)
        ((float4*)sin_)[i] = ((const float4*)src)[i];
    __syncthreads();
    int w = threadIdx.x>>5, lane = threadIdx.x&31;
    u64 acc[8][2];
    #pragma unroll
    for(int i=0;i<8;i++){ acc[i][0]=0ull; acc[i][1]=0ull; }
    for(int k=0;k<128;k++){
        float4 wf = *(const float4*)&W[k*128 + lane*4];
        u64 w0=pk(wf.x,wf.y), w1=pk(wf.z,wf.w);
        #pragma unroll
        for(int i=0;i<8;i++){
            float v = sin_[(w*8+i)*128 + k];
            u64 vp = pk(v,v);
            fma2(acc[i][0],vp,w0); fma2(acc[i][1],vp,w1);
        }
    }
    float* dst = out + (size_t)d*NH + (size_t)n0*HH;
    #pragma unroll
    for(int i=0;i<8;i++){
        float4 o; upk(acc[i][0],o.x,o.y); upk(acc[i][1],o.z,o.w);
        *(float4*)&dst[(w*8+i)*HH + lane*4] = o;
    }
}

// ---------------- edge MLP via mma.sync tf32 (hi/lo), warps partition OUTPUTS ----
// Block: 256 threads = 8 warps, 128 edges/block. Weight loads software-pipelined
// (distance-1 prefetch, static double buffers) to hide L2 latency at occ=1.
#define H1PAD 132
#define H2PAD 260
#define MLP_SMEMF (128 + 128*H1PAD + 128*H2PAD)

__global__ void __launch_bounds__(256,1)
k_mlp_mma(const float* __restrict__ attr, const float* __restrict__ ewt,
          const float* __restrict__ b1, const float* __restrict__ b2,
          const float* __restrict__ b3raw, int l){
    extern __shared__ float sm[];
    float* cv = sm;
    float* h1 = sm + 128;
    float* h2 = sm + 128 + 128*H1PAD;
    float* s_attr = h2;               // alias: 128 x 36, stage-1 input only
    int tid = threadIdx.x;
    int warp = tid>>5, lane = tid&31;
    int g = lane>>2, t = lane&3;
    int eblk = blockIdx.x*128;

    const float2* W1 = (const float2*)g_W1hl + (size_t)l*4096;
    const float2* W2 = (const float2*)g_W2hl + (size_t)l*32768;
    const float2* W3 = (const float2*)g_W3hl + (size_t)l*98304;

    // stage attr into smem (pad 36 -> conflict-free (4g+t) fragment reads)
    for(int i=tid;i<1024;i+=256){
        int e=i>>3, k4=(i&7)<<2;
        float4 v = *(const float4*)&attr[(size_t)(eblk+e)*32 + k4];
        *(float4*)&s_attr[e*36 + k4] = v;
    }
    if(tid<128){
        float wv = ewt[eblk+tid];
        cv[tid] = (wv < CUT) ? 0.5f*(cosf(wv*(3.14159265358979f/CUT))+1.f) : 0.f;
    }
    __syncthreads();

    // ---- stage 1: outputs [16w,16w+16), all 128 edges, K=32 (weights L1-hot) ----
    {
        float d[2][8][4];
        #pragma unroll
        for(int m=0;m<2;m++)
            #pragma unroll
            for(int nt=0;nt<8;nt++){ d[m][nt][0]=d[m][nt][1]=d[m][nt][2]=d[m][nt][3]=0.f; }
        int o = warp*16;
        float2 wa[2][4], wb[2][4];
        ldw(W1,32,o,0,g,t,wa[0]);
        #pragma unroll
        for(int kc=0;kc<4;kc+=2){
            ldw(W1,32,o,(kc+1)*8,g,t,wb[0]);
            // two edge-halves share the same weights: m-index abused as edge-half
            do_mma<1>(reinterpret_cast<float(&)[1][8][4]>(d[0]),
                      reinterpret_cast<const float2(&)[1][4]>(wa[0]), s_attr, 36, 0,  kc*8, g, t);
            do_mma<1>(reinterpret_cast<float(&)[1][8][4]>(d[1]),
                      reinterpret_cast<const float2(&)[1][4]>(wa[0]), s_attr, 36, 64, kc*8, g, t);
            if(kc+2<4) ldw(W1,32,o,(kc+2)*8,g,t,wa[0]);
            do_mma<1>(reinterpret_cast<float(&)[1][8][4]>(d[0]),
                      reinterpret_cast<const float2(&)[1][4]>(wb[0]), s_attr, 36, 0,  (kc+1)*8, g, t);
            do_mma<1>(reinterpret_cast<float(&)[1][8][4]>(d[1]),
                      reinterpret_cast<const float2(&)[1][4]>(wb[0]), s_attr, 36, 64, (kc+1)*8, g, t);
        }
        float bA=b1[o+g], bB=b1[o+g+8];
        #pragma unroll
        for(int hf=0;hf<2;hf++)
            #pragma unroll
            for(int nt=0;nt<8;nt++){
                int e = hf*64 + nt*8 + 2*t;
                h1[e*H1PAD + o+g]       = siluf(d[hf][nt][0]+bA);
                h1[(e+1)*H1PAD + o+g]   = siluf(d[hf][nt][1]+bA);
                h1[e*H1PAD + o+g+8]     = siluf(d[hf][nt][2]+bB);
                h1[(e+1)*H1PAD + o+g+8] = siluf(d[hf][nt][3]+bB);
            }
    }
    __syncthreads();

    // ---- stage 2: outputs [32w,32w+32) (2 m-tiles), K=128, prefetched weights ----
    #pragma unroll 1
    for(int half=0; half<2; half++){
        float d[2][8][4];
        #pragma unroll
        for(int m=0;m<2;m++)
            #pragma unroll
            for(int nt=0;nt<8;nt++){ d[m][nt][0]=d[m][nt][1]=d[m][nt][2]=d[m][nt][3]=0.f; }
        int o = warp*32;
        float2 wa[2][4], wb[2][4];
        ldw(W2,128,o,0,g,t,wa[0]); ldw(W2,128,o+16,0,g,t,wa[1]);
        #pragma unroll 1
        for(int kc=0;kc<16;kc+=2){
            ldw(W2,128,o,(kc+1)*8,g,t,wb[0]); ldw(W2,128,o+16,(kc+1)*8,g,t,wb[1]);
            do_mma<2>(d, wa, h1, H1PAD, half*64, kc*8, g, t);
            if(kc+2<16){ ldw(W2,128,o,(kc+2)*8,g,t,wa[0]); ldw(W2,128,o+16,(kc+2)*8,g,t,wa[1]); }
            do_mma<2>(d, wb, h1, H1PAD, half*64, (kc+1)*8, g, t);
        }
        #pragma unroll
        for(int m=0;m<2;m++){
            int oo = warp*32 + m*16;
            float bA=b2[oo+g], bB=b2[oo+g+8];
            #pragma unroll
            for(int nt=0;nt<8;nt++){
                int e = half*64 + nt*8 + 2*t;
                h2[e*H2PAD + oo+g]       = siluf(d[m][nt][0]+bA);
                h2[(e+1)*H2PAD + oo+g]   = siluf(d[m][nt][1]+bA);
                h2[e*H2PAD + oo+g+8]     = siluf(d[m][nt][2]+bB);
                h2[(e+1)*H2PAD + oo+g+8] = siluf(d[m][nt][3]+bB);
            }
        }
    }
    __syncthreads();

    // ---- stage 3: outputs [48w,48w+48) (3 m-tiles), K=256, prefetched weights ----
    #pragma unroll 1
    for(int half=0; half<2; half++){
        float d[3][8][4];
        #pragma unroll
        for(int m=0;m<3;m++)
            #pragma unroll
            for(int nt=0;nt<8;nt++){ d[m][nt][0]=d[m][nt][1]=d[m][nt][2]=d[m][nt][3]=0.f; }
        int o = warp*48;
        float2 wa[3][4], wb[3][4];
        #pragma unroll
        for(int m=0;m<3;m++) ldw(W3,256,o+m*16,0,g,t,wa[m]);
        #pragma unroll 1
        for(int kc=0;kc<32;kc+=2){
            #pragma unroll
            for(int m=0;m<3;m++) ldw(W3,256,o+m*16,(kc+1)*8,g,t,wb[m]);
            do_mma<3>(d, wa, h2, H2PAD, half*64, kc*8, g, t);
            if(kc+2<32){
                #pragma unroll
                for(int m=0;m<3;m++) ldw(W3,256,o+m*16,(kc+2)*8,g,t,wa[m]);
            }
            do_mma<3>(d, wb, h2, H2PAD, half*64, (kc+1)*8, g, t);
        }
        #pragma unroll
        for(int m=0;m<3;m++){
            int oA = warp*48 + m*16 + g, oB = oA + 8;
            float bA = b3raw[(oA&127)*3 + (oA>>7)];
            float bB = b3raw[(oB&127)*3 + (oB>>7)];
            #pragma unroll
            for(int nt=0;nt<8;nt++){
                int e0 = half*64 + nt*8 + 2*t;
                float c0 = cv[e0], c1 = cv[e0+1];
                float* ep0 = g_ea + (size_t)(eblk+e0)*384;
                float* ep1 = g_ea + (size_t)(eblk+e0+1)*384;
                ep0[oA] = siluf(d[m][nt][0]+bA)*c0;
                ep1[oA] = siluf(d[m][nt][1]+bA)*c1;
                ep0[oB] = siluf(d[m][nt][2]+bB)*c0;
                ep1[oB] = siluf(d[m][nt][3]+bB)*c1;
            }
        }
    }
}

// ---------------- gather segment-sum + O(3) node update ----------------
__global__ void __launch_bounds__(128) k_gather_update(const int* __restrict__ ei,
                                                       const float* __restrict__ q){
    int n = blockIdx.x;
    int h = threadIdx.x;
    int s = g_row[n], e1 = g_row[n+1];
    float cm[9];
    #pragma unroll
    for(int d=0;d<9;d++) cm[d]=0.f;
    for(int t=s;t<e1;t++){
        int e = g_eord[t];
        int dst = ei[NE + e];
        const float* ep = g_ea + (size_t)e*384;
        float a0=ep[h], a1=ep[128+h], a2=ep[256+h];
        int di = dst*HH + h;
        cm[0] += a0*g_cM[0*NH+di];
        cm[1] += a1*g_cM[1*NH+di];
        cm[2] += a1*g_cM[2*NH+di];
        cm[3] += a1*g_cM[3*NH+di];
        cm[4] += a2*g_cM[4*NH+di];
        cm[5] += a2*g_cM[5*NH+di];
        cm[6] += a2*g_cM[6*NH+di];
        cm[7] += a2*g_cM[7*NH+di];
        cm[8] += a2*g_cM[8*NH+di];
    }
    int idx = n*HH + h;
    float cy[9];
    #pragma unroll
    for(int d=0;d<9;d++) cy[d]=g_cM[d*NH+idx];
    float M[9], Y[9];
    rec(cm,M); rec(cy,Y);
    float AB[9];
    #pragma unroll
    for(int r=0;r<9;r++) AB[r]=0.f;
    mmadd(M,Y,AB); mmadd(Y,M,AB);
    float f = 1.f + 0.1f*q[n];
    float T[9]; float nrm=0.f;
    #pragma unroll
    for(int r=0;r<9;r++){ T[r]=f*AB[r]; nrm += T[r]*T[r]; }
    float inv = 1.f/(nrm+1.f);
    float c2[9]; tocompact(T,inv,c2);
    #pragma unroll
    for(int d=0;d<9;d++) g_c2[d*NH+idx]=c2[d];
}

// ---------------- final node update ----------------
__global__ void k_upd_b(const float* __restrict__ q, float* __restrict__ Xout){
    int idx = blockIdx.x*blockDim.x + threadIdx.x;
    if(idx>=NH) return;
    float c[9];
    #pragma unroll
    for(int d=0;d<9;d++) c[d]=g_dXc[d*NH+idx];
    float dx[9]; rec(c,dx);
    float f = 1.f + 0.1f*q[idx>>7];
    float D2[9];
    #pragma unroll
    for(int r=0;r<9;r++) D2[r]=0.f;
    mmadd(dx,dx,D2);
    #pragma unroll
    for(int r=0;r<9;r++)
        Xout[(size_t)idx*9+r] = g_Xn[(size_t)idx*9+r] + dx[r] + f*D2[r];
}

// ---------------- launcher ----------------
// Launch order puts k_mlp_mma at index 5 so ncu's "-s 5 -c 1" window catches it.
extern "C" void kernel_launch(void* const* d_in, const int* in_sizes, int n_in,
                              void* d_out, int out_size){
    const float* X    = (const float*)d_in[0];
    const float* attr = (const float*)d_in[1];
    const float* ewt  = (const float*)d_in[2];
    const float* q    = (const float*)d_in[3];
    const float* Ws1  = (const float*)d_in[4];
    const float* bs1  = (const float*)d_in[5];
    const float* Ws2  = (const float*)d_in[6];
    const float* bs2  = (const float*)d_in[7];
    const float* Ws3  = (const float*)d_in[8];
    const float* bs3  = (const float*)d_in[9];
    const float* Wt   = (const float*)d_in[10];
    const int*   ei   = (const int*)d_in[11];
    float* out = (float*)d_out;

    cudaFuncSetAttribute(k_mlp_mma, cudaFuncAttributeMaxDynamicSharedMemorySize,
                         MLP_SMEMF*4);

    // layer 0, with CSR build interleaved after the MLP launch (deps allow it)
    k_prep_w<<<264,256>>>(Ws1,Ws2,Ws3,Wt);                                   // 0
    k_node_prep<<<NH/256,256>>>(X);                                          // 1
    k_mix<<<dim3(64,9),128>>>(0, 0);                                         // 2
    k_zero_cnt<<<(NA+255)/256,256>>>();                                      // 3
    k_count<<<NE/256,256>>>(ei);                                             // 4
    k_mlp_mma<<<NE/128,256,MLP_SMEMF*4>>>(attr, ewt, bs1, bs2, bs3, 0);      // 5 <- ncu
    k_scan<<<1,1024>>>();                                                    // 6
    k_place<<<NE/256,256>>>(ei);                                             // 7
    k_gather_update<<<NA,128>>>(ei, q);                                      // 8
    k_mix<<<dim3(64,9),128>>>(1, 3);                                         // 9
    k_upd_b<<<NH/256,256>>>(q, out);                                         // 10

    // layer 1 (CSR already built)
    k_node_prep<<<NH/256,256>>>(out);
    k_mix<<<dim3(64,9),128>>>(0, 6);
    k_mlp_mma<<<NE/128,256,MLP_SMEMF*4>>>(attr, ewt, bs1+128, bs2+256, bs3+384, 1);
    k_gather_update<<<NA,128>>>(ei, q);
    k_mix<<<dim3(64,9),128>>>(1, 9);
    k_upd_b<<<NH/256,256>>>(q, out);
}

// round 7
// speedup vs baseline: 2.4486x; 1.5415x over previous
#include <cuda_runtime.h>
#include <cstdint>
#include <cstddef>

#define NA 2048
#define HH 128
#define NE 32768
#define RR 32
#define NH (NA*HH)
#define CUT 4.5f

// ---------------- scratch (static device globals; no allocations) ----------------
__device__ float g_ea[NE*384];          // edge MLP output, layout [e][3][128] (float)
__device__ float g_Xn[NH*9];
__device__ float g_cA[9*NH];
__device__ float g_cM[9*NH];
__device__ float g_c2[9*NH];
__device__ float g_dXc[9*NH];
__device__ unsigned g_W1f[2*8*2*32*8];      // bf16 hi/lo fragment images
__device__ unsigned g_W2f[2*16*8*32*8];
__device__ unsigned g_W3f[2*24*16*32*8];    // W3 output-permuted: o' = c*128+h
__device__ float g_WtT[12*HH*HH];
__device__ int   g_cnt[NA];
__device__ int   g_cur[NA];
__device__ int   g_row[NA+1];
__device__ int   g_eord[NE];

typedef unsigned long long u64;
typedef unsigned u32;

// ---------------- generic helpers ----------------
__device__ __forceinline__ u64 pk(float a, float b){
    u64 r; asm("mov.b64 %0, {%1,%2};" : "=l"(r) : "f"(a), "f"(b)); return r;
}
__device__ __forceinline__ void upk(u64 v, float& a, float& b){
    asm("mov.b64 {%0,%1}, %2;" : "=f"(a), "=f"(b) : "l"(v));
}
__device__ __forceinline__ void fma2(u64& d, u64 a, u64 b){
    asm("fma.rn.f32x2 %0, %1, %2, %0;" : "+l"(d) : "l"(a), "l"(b));
}
__device__ __forceinline__ float siluf(float x){ return x / (1.f + __expf(-x)); }
__device__ __forceinline__ u32 prmt(u32 a, u32 b, u32 s){
    u32 d; asm("prmt.b32 %0,%1,%2,%3;" : "=r"(d) : "r"(a),"r"(b),"r"(s)); return d;
}

// split fp32 into packed (hi,lo) bf16 pair: low16 = hi bits, high16 = lo bits
__device__ __forceinline__ u32 pack_hl(float v){
    u32 u = __float_as_uint(v);
    float r = v - __uint_as_float(u & 0xFFFF0000u);   // exact residual
    return prmt(u, __float_as_uint(r), 0x7632);
}

// bf16 m16n8k16 mma: D(16x8) += A(16x16,row) * B(16x8,col)
__device__ __forceinline__ void mma16(float* d, const u32* a, const u32* b){
    asm volatile("mma.sync.aligned.m16n8k16.row.col.f32.bf16.bf16.f32 "
        "{%0,%1,%2,%3}, {%4,%5,%6,%7}, {%8,%9}, {%0,%1,%2,%3};"
        : "+f"(d[0]),"+f"(d[1]),"+f"(d[2]),"+f"(d[3])
        : "r"(a[0]),"r"(a[1]),"r"(a[2]),"r"(a[3]), "r"(b[0]),"r"(b[1]));
}

struct WF { uint4 h, l; };
__device__ __forceinline__ void ldwf(const uint4* __restrict__ W, int idx, WF& w){
    w.h = W[idx*2]; w.l = W[idx*2+1];
}

// one K=16 chunk over M m-tiles x 8 edge-tiles; acts packed (hi,lo) u32 in smem
template<int M>
__device__ __forceinline__ void do_mma16(float (&d)[M][8][4], const WF (&w)[M],
                                         const u32* __restrict__ act, int pad,
                                         int ebase, int k0, int g, int t){
    #pragma unroll
    for(int nt=0;nt<8;nt++){
        int e = ebase + nt*8 + g;
        uint2 q0 = *(const uint2*)&act[e*pad + k0 + 2*t];
        uint2 q1 = *(const uint2*)&act[e*pad + k0 + 2*t + 8];
        u32 bh[2], bl[2];
        bh[0]=prmt(q0.x,q0.y,0x5410); bl[0]=prmt(q0.x,q0.y,0x7632);
        bh[1]=prmt(q1.x,q1.y,0x5410); bl[1]=prmt(q1.x,q1.y,0x7632);
        #pragma unroll
        for(int m=0;m<M;m++){
            const u32* ah = (const u32*)&w[m].h;
            const u32* al = (const u32*)&w[m].l;
            mma16(d[m][nt],ah,bh); mma16(d[m][nt],ah,bl); mma16(d[m][nt],al,bh);
        }
    }
}

// compact basis: {i0, a01, a02, a12, s00, s01, s02, s11, s12}
__device__ __forceinline__ void tocompact(const float* t, float s, float* c){
    float i0 = (t[0]+t[4]+t[8])*(1.f/3.f);
    c[0] = i0*s;
    c[1] = 0.5f*(t[1]-t[3])*s;
    c[2] = 0.5f*(t[2]-t[6])*s;
    c[3] = 0.5f*(t[5]-t[7])*s;
    c[4] = (t[0]-i0)*s;
    c[5] = 0.5f*(t[1]+t[3])*s;
    c[6] = 0.5f*(t[2]+t[6])*s;
    c[7] = (t[4]-i0)*s;
    c[8] = 0.5f*(t[5]+t[7])*s;
}
__device__ __forceinline__ void rec(const float* c, float* t){
    float i0=c[0], a01=c[1], a02=c[2], a12=c[3];
    float s00=c[4], s01=c[5], s02=c[6], s11=c[7], s12=c[8];
    t[0]=i0+s00;  t[1]=a01+s01; t[2]=a02+s02;
    t[3]=s01-a01; t[4]=i0+s11;  t[5]=a12+s12;
    t[6]=s02-a02; t[7]=s12-a12; t[8]=i0-s00-s11;
}
__device__ __forceinline__ void mmadd(const float* A, const float* B, float* C){
    #pragma unroll
    for(int i=0;i<3;i++){
        #pragma unroll
        for(int j=0;j<3;j++)
            C[i*3+j] += A[i*3+0]*B[0*3+j] + A[i*3+1]*B[1*3+j] + A[i*3+2]*B[2*3+j];
    }
}

// ---------------- weight prep: bf16 hi/lo fragment images + WtT ----------------
// fragment regs: a0=(row g, k=2t,2t+1) a1=(row g+8, same k) a2=(row g, k+8) a3=(row g+8, k+8)
__device__ __forceinline__ void packw(const float* __restrict__ W, int stride,
                                      int r, int k, u32& hi, u32& lo){
    float w0=W[r*stride+k], w1=W[r*stride+k+1];
    u32 u0=__float_as_uint(w0), u1=__float_as_uint(w1);
    float r0=w0-__uint_as_float(u0&0xFFFF0000u);
    float r1=w1-__uint_as_float(u1&0xFFFF0000u);
    hi = (u0>>16) | (__float_as_uint(w1)&0xFFFF0000u);
    lo = (__float_as_uint(r0)>>16) | (__float_as_uint(r1)&0xFFFF0000u);
    (void)u1;
}

__global__ void k_prep_w(const float* __restrict__ Ws1, const float* __restrict__ Ws2,
                         const float* __restrict__ Ws3, const float* __restrict__ Wt){
    int stride = gridDim.x*blockDim.x;
    int t0 = blockIdx.x*blockDim.x + threadIdx.x;
    // W1 frags: [l][ot(8)][kc(2)][lane]
    for(int i=t0;i<2*8*2*32;i+=stride){
        int l=i>>9, r=i&511, ot=r>>6, r2=r&63, kc=r2>>5, lane=r2&31;
        int g=lane>>2, t=lane&3, o0=ot*16, kb=kc*16;
        const float* W = Ws1 + (size_t)l*128*32;
        u32 f[8];
        packw(W,32,o0+g,  kb+2*t,  f[0],f[4]);
        packw(W,32,o0+g+8,kb+2*t,  f[1],f[5]);
        packw(W,32,o0+g,  kb+2*t+8,f[2],f[6]);
        packw(W,32,o0+g+8,kb+2*t+8,f[3],f[7]);
        u32* dst = g_W1f + ((size_t)l*512 + (ot*2+kc)*32 + lane)*8;
        #pragma unroll
        for(int j=0;j<8;j++) dst[j]=f[j];
    }
    // W2 frags: [l][ot(16)][kc(8)][lane]
    for(int i=t0;i<2*16*8*32;i+=stride){
        int l=i>>12, r=i&4095, ot=r>>8, r2=r&255, kc=r2>>5, lane=r2&31;
        int g=lane>>2, t=lane&3, o0=ot*16, kb=kc*16;
        const float* W = Ws2 + (size_t)l*256*128;
        u32 f[8];
        packw(W,128,o0+g,  kb+2*t,  f[0],f[4]);
        packw(W,128,o0+g+8,kb+2*t,  f[1],f[5]);
        packw(W,128,o0+g,  kb+2*t+8,f[2],f[6]);
        packw(W,128,o0+g+8,kb+2*t+8,f[3],f[7]);
        u32* dst = g_W2f + ((size_t)l*4096 + (ot*8+kc)*32 + lane)*8;
        #pragma unroll
        for(int j=0;j<8;j++) dst[j]=f[j];
    }
    // W3 frags (output-permuted rows): [l][ot(24)][kc(16)][lane]
    for(int i=t0;i<2*24*16*32;i+=stride){
        int l=i/12288, r=i%12288, ot=r>>9, r2=r&511, kc=r2>>5, lane=r2&31;
        int g=lane>>2, t=lane&3, o0=ot*16, kb=kc*16;
        const float* W = Ws3 + (size_t)l*384*256;
        int rows[2] = { o0+g, o0+g+8 };
        u32 f[8];
        #pragma unroll
        for(int rr=0;rr<2;rr++){
            int op = rows[rr];
            int j = (op&127)*3 + (op>>7);          // source row in Ws3
            packw(W,256,j,kb+2*t,  f[rr],  f[rr+4]);
            packw(W,256,j,kb+2*t+8,f[rr+2],f[rr+6]);
        }
        u32* dst = g_W3f + ((size_t)l*12288 + (ot*16+kc)*32 + lane)*8;
        #pragma unroll
        for(int j=0;j<8;j++) dst[j]=f[j];
    }
    for(int i=t0;i<12*128*128;i+=stride){
        int lm=i/16384, r=i%16384, g=r/128, hh=r%128;
        g_WtT[lm*16384 + hh*128 + g] = Wt[i];
    }
}

// ---------------- CSR build ----------------
__global__ void k_zero_cnt(){
    int i = blockIdx.x*blockDim.x + threadIdx.x;
    if(i<NA){ g_cnt[i]=0; g_cur[i]=0; }
}
__global__ void k_count(const int* __restrict__ ei){
    int e = blockIdx.x*blockDim.x + threadIdx.x;
    if(e<NE) atomicAdd(&g_cnt[ei[e]], 1);
}
__global__ void k_scan(){
    __shared__ int sh[1024];
    int t = threadIdx.x;
    int v0 = g_cnt[2*t], v1 = g_cnt[2*t+1];
    int s = v0+v1;
    sh[t]=s; __syncthreads();
    #pragma unroll
    for(int off=1; off<1024; off<<=1){
        int x = (t>=off)? sh[t-off] : 0;
        __syncthreads();
        sh[t] += x;
        __syncthreads();
    }
    int incl = sh[t];
    int excl = incl - s;
    g_row[2*t]   = excl;
    g_row[2*t+1] = excl + v0;
    if(t==1023) g_row[2048]=incl;
}
__global__ void k_place(const int* __restrict__ ei){
    int e = blockIdx.x*blockDim.x + threadIdx.x;
    if(e<NE){
        int s = ei[e];
        int p = atomicAdd(&g_cur[s],1);
        g_eord[g_row[s]+p] = e;
    }
}

// ---------------- node prep ----------------
__global__ void k_node_prep(const float* __restrict__ Xin){
    int idx = blockIdx.x*blockDim.x + threadIdx.x;
    if(idx>=NH) return;
    float t[9]; float nrm=0.f;
    #pragma unroll
    for(int r=0;r<9;r++){ t[r]=Xin[(size_t)idx*9+r]; nrm += t[r]*t[r]; }
    float inv = 1.f/(nrm+1.f);
    #pragma unroll
    for(int r=0;r<9;r++){ t[r]*=inv; g_Xn[(size_t)idx*9+r]=t[r]; }
    float c[9]; tocompact(t,1.f,c);
    #pragma unroll
    for(int d=0;d<9;d++) g_cA[d*NH+idx]=c[d];
}

// ---------------- channel mix (f32x2) ----------------
__global__ void __launch_bounds__(128) k_mix(int which, int wbase){
    __shared__ float sin_[32*128];
    const float* in  = which ? g_c2  : g_cA;
    float*       out = which ? g_dXc : g_cM;
    int d = blockIdx.y;
    int m = (d==0)?0:((d<4)?1:2);
    const float* W = g_WtT + (size_t)(wbase+m)*16384;
    int n0 = blockIdx.x*32;
    const float* src = in + (size_t)d*NH + (size_t)n0*HH;
    for(int i=threadIdx.x;i<1024;i+=128)
        ((float4*)sin_)[i] = ((const float4*)src)[i];
    __syncthreads();
    int w = threadIdx.x>>5, lane = threadIdx.x&31;
    u64 acc[8][2];
    #pragma unroll
    for(int i=0;i<8;i++){ acc[i][0]=0ull; acc[i][1]=0ull; }
    for(int k=0;k<128;k++){
        float4 wf = *(const float4*)&W[k*128 + lane*4];
        u64 w0=pk(wf.x,wf.y), w1=pk(wf.z,wf.w);
        #pragma unroll
        for(int i=0;i<8;i++){
            float v = sin_[(w*8+i)*128 + k];
            u64 vp = pk(v,v);
            fma2(acc[i][0],vp,w0); fma2(acc[i][1],vp,w1);
        }
    }
    float* dst = out + (size_t)d*NH + (size_t)n0*HH;
    #pragma unroll
    for(int i=0;i<8;i++){
        float4 o; upk(acc[i][0],o.x,o.y); upk(acc[i][1],o.z,o.w);
        *(float4*)&dst[(w*8+i)*HH + lane*4] = o;
    }
}

// ---------------- edge MLP via bf16 split mma (warps partition outputs) -------
// smem u32 layout: cv[128] | h1[128][136] | h2[128][264]; attr aliases h2 (pad 40).
#define H1PAD 136
#define H2PAD 264
#define APAD  40
#define MLP_SMEMW (128 + 128*H1PAD + 128*H2PAD)

__global__ void __launch_bounds__(256,1)
k_mlp_mma(const float* __restrict__ attr, const float* __restrict__ ewt,
          const float* __restrict__ b1, const float* __restrict__ b2,
          const float* __restrict__ b3raw, int l){
    extern __shared__ u32 smu[];
    float* cv = (float*)smu;
    u32* h1 = smu + 128;
    u32* h2 = smu + 128 + 128*H1PAD;
    u32* s_attr = h2;                  // alias, stage-1 only
    int tid = threadIdx.x;
    int warp = tid>>5, lane = tid&31;
    int g = lane>>2, t = lane&3;
    int eblk = blockIdx.x*128;

    const uint4* W1 = (const uint4*)(g_W1f + (size_t)l*4096);
    const uint4* W2 = (const uint4*)(g_W2f + (size_t)l*32768);
    const uint4* W3 = (const uint4*)(g_W3f + (size_t)l*98304);

    // stage attr, pre-split packed
    for(int i=tid;i<1024;i+=256){
        int e=i>>3, k4=(i&7)<<2;
        float4 v = *(const float4*)&attr[(size_t)(eblk+e)*32 + k4];
        uint4 p = make_uint4(pack_hl(v.x),pack_hl(v.y),pack_hl(v.z),pack_hl(v.w));
        *(uint4*)&s_attr[e*APAD + k4] = p;
    }
    if(tid<128){
        float wv = ewt[eblk+tid];
        cv[tid] = (wv < CUT) ? 0.5f*(cosf(wv*(3.14159265358979f/CUT))+1.f) : 0.f;
    }
    __syncthreads();

    // ---- stage 1: outputs [16w,16w+16), K=32 (2 chunks), 128 edges ----
    {
        float d0[1][8][4], d1[1][8][4];
        #pragma unroll
        for(int nt=0;nt<8;nt++)
            #pragma unroll
            for(int j=0;j<4;j++){ d0[0][nt][j]=0.f; d1[0][nt][j]=0.f; }
        WF wa[1];
        #pragma unroll
        for(int kc=0;kc<2;kc++){
            ldwf(W1, (warp*2+kc)*32+lane, wa[0]);
            do_mma16<1>(d0, wa, s_attr, APAD, 0,  kc*16, g, t);
            do_mma16<1>(d1, wa, s_attr, APAD, 64, kc*16, g, t);
        }
        int o = warp*16;
        float bA=b1[o+g], bB=b1[o+g+8];
        #pragma unroll
        for(int hf=0;hf<2;hf++){
            float (*dd)[8][4] = hf? d1 : d0;
            #pragma unroll
            for(int nt=0;nt<8;nt++){
                int e = hf*64 + nt*8 + 2*t;
                h1[e*H1PAD + o+g]       = pack_hl(siluf(dd[0][nt][0]+bA));
                h1[(e+1)*H1PAD + o+g]   = pack_hl(siluf(dd[0][nt][1]+bA));
                h1[e*H1PAD + o+g+8]     = pack_hl(siluf(dd[0][nt][2]+bB));
                h1[(e+1)*H1PAD + o+g+8] = pack_hl(siluf(dd[0][nt][3]+bB));
            }
        }
    }
    __syncthreads();

    // ---- stage 2: outputs [32w,32w+32) (2 m-tiles), K=128 (8 chunks) ----
    #pragma unroll 1
    for(int half=0; half<2; half++){
        float d[2][8][4];
        #pragma unroll
        for(int m=0;m<2;m++)
            #pragma unroll
            for(int nt=0;nt<8;nt++){ d[m][nt][0]=d[m][nt][1]=d[m][nt][2]=d[m][nt][3]=0.f; }
        WF wa[2], wb[2];
        #pragma unroll
        for(int m=0;m<2;m++) ldwf(W2, ((warp*2+m)*8+0)*32+lane, wa[m]);
        #pragma unroll 1
        for(int kc=0;kc<8;kc+=2){
            #pragma unroll
            for(int m=0;m<2;m++) ldwf(W2, ((warp*2+m)*8+kc+1)*32+lane, wb[m]);
            do_mma16<2>(d, wa, h1, H1PAD, half*64, kc*16, g, t);
            if(kc+2<8){
                #pragma unroll
                for(int m=0;m<2;m++) ldwf(W2, ((warp*2+m)*8+kc+2)*32+lane, wa[m]);
            }
            do_mma16<2>(d, wb, h1, H1PAD, half*64, (kc+1)*16, g, t);
        }
        #pragma unroll
        for(int m=0;m<2;m++){
            int oo = warp*32 + m*16;
            float bA=b2[oo+g], bB=b2[oo+g+8];
            #pragma unroll
            for(int nt=0;nt<8;nt++){
                int e = half*64 + nt*8 + 2*t;
                h2[e*H2PAD + oo+g]       = pack_hl(siluf(d[m][nt][0]+bA));
                h2[(e+1)*H2PAD + oo+g]   = pack_hl(siluf(d[m][nt][1]+bA));
                h2[e*H2PAD + oo+g+8]     = pack_hl(siluf(d[m][nt][2]+bB));
                h2[(e+1)*H2PAD + oo+g+8] = pack_hl(siluf(d[m][nt][3]+bB));
            }
        }
    }
    __syncthreads();

    // ---- stage 3: outputs [48w,48w+48) (3 m-tiles), K=256 (16 chunks) ----
    #pragma unroll 1
    for(int half=0; half<2; half++){
        float d[3][8][4];
        #pragma unroll
        for(int m=0;m<3;m++)
            #pragma unroll
            for(int nt=0;nt<8;nt++){ d[m][nt][0]=d[m][nt][1]=d[m][nt][2]=d[m][nt][3]=0.f; }
        WF wa[3], wb[3];
        #pragma unroll
        for(int m=0;m<3;m++) ldwf(W3, ((warp*3+m)*16+0)*32+lane, wa[m]);
        #pragma unroll 1
        for(int kc=0;kc<16;kc+=2){
            #pragma unroll
            for(int m=0;m<3;m++) ldwf(W3, ((warp*3+m)*16+kc+1)*32+lane, wb[m]);
            do_mma16<3>(d, wa, h2, H2PAD, half*64, kc*16, g, t);
            if(kc+2<16){
                #pragma unroll
                for(int m=0;m<3;m++) ldwf(W3, ((warp*3+m)*16+kc+2)*32+lane, wa[m]);
            }
            do_mma16<3>(d, wb, h2, H2PAD, half*64, (kc+1)*16, g, t);
        }
        #pragma unroll
        for(int m=0;m<3;m++){
            int oA = warp*48 + m*16 + g, oB = oA + 8;
            float bA = b3raw[(oA&127)*3 + (oA>>7)];
            float bB = b3raw[(oB&127)*3 + (oB>>7)];
            #pragma unroll
            for(int nt=0;nt<8;nt++){
                int e0 = half*64 + nt*8 + 2*t;
                float c0 = cv[e0], c1 = cv[e0+1];
                float* ep0 = g_ea + (size_t)(eblk+e0)*384;
                float* ep1 = g_ea + (size_t)(eblk+e0+1)*384;
                ep0[oA] = siluf(d[m][nt][0]+bA)*c0;
                ep1[oA] = siluf(d[m][nt][1]+bA)*c1;
                ep0[oB] = siluf(d[m][nt][2]+bB)*c0;
                ep1[oB] = siluf(d[m][nt][3]+bB)*c1;
            }
        }
    }
}

// ---------------- gather segment-sum + O(3) node update ----------------
__global__ void __launch_bounds__(128) k_gather_update(const int* __restrict__ ei,
                                                       const float* __restrict__ q){
    int n = blockIdx.x;
    int h = threadIdx.x;
    int s = g_row[n], e1 = g_row[n+1];
    float cm[9];
    #pragma unroll
    for(int d=0;d<9;d++) cm[d]=0.f;
    for(int t=s;t<e1;t++){
        int e = g_eord[t];
        int dst = ei[NE + e];
        const float* ep = g_ea + (size_t)e*384;
        float a0=ep[h], a1=ep[128+h], a2=ep[256+h];
        int di = dst*HH + h;
        cm[0] += a0*g_cM[0*NH+di];
        cm[1] += a1*g_cM[1*NH+di];
        cm[2] += a1*g_cM[2*NH+di];
        cm[3] += a1*g_cM[3*NH+di];
        cm[4] += a2*g_cM[4*NH+di];
        cm[5] += a2*g_cM[5*NH+di];
        cm[6] += a2*g_cM[6*NH+di];
        cm[7] += a2*g_cM[7*NH+di];
        cm[8] += a2*g_cM[8*NH+di];
    }
    int idx = n*HH + h;
    float cy[9];
    #pragma unroll
    for(int d=0;d<9;d++) cy[d]=g_cM[d*NH+idx];
    float M[9], Y[9];
    rec(cm,M); rec(cy,Y);
    float AB[9];
    #pragma unroll
    for(int r=0;r<9;r++) AB[r]=0.f;
    mmadd(M,Y,AB); mmadd(Y,M,AB);
    float f = 1.f + 0.1f*q[n];
    float T[9]; float nrm=0.f;
    #pragma unroll
    for(int r=0;r<9;r++){ T[r]=f*AB[r]; nrm += T[r]*T[r]; }
    float inv = 1.f/(nrm+1.f);
    float c2[9]; tocompact(T,inv,c2);
    #pragma unroll
    for(int d=0;d<9;d++) g_c2[d*NH+idx]=c2[d];
}

// ---------------- final node update ----------------
__global__ void k_upd_b(const float* __restrict__ q, float* __restrict__ Xout){
    int idx = blockIdx.x*blockDim.x + threadIdx.x;
    if(idx>=NH) return;
    float c[9];
    #pragma unroll
    for(int d=0;d<9;d++) c[d]=g_dXc[d*NH+idx];
    float dx[9]; rec(c,dx);
    float f = 1.f + 0.1f*q[idx>>7];
    float D2[9];
    #pragma unroll
    for(int r=0;r<9;r++) D2[r]=0.f;
    mmadd(dx,dx,D2);
    #pragma unroll
    for(int r=0;r<9;r++)
        Xout[(size_t)idx*9+r] = g_Xn[(size_t)idx*9+r] + dx[r] + f*D2[r];
}

// ---------------- launcher (MLP at launch index 3 for the ncu window) ----------
extern "C" void kernel_launch(void* const* d_in, const int* in_sizes, int n_in,
                              void* d_out, int out_size){
    const float* X    = (const float*)d_in[0];
    const float* attr = (const float*)d_in[1];
    const float* ewt  = (const float*)d_in[2];
    const float* q    = (const float*)d_in[3];
    const float* Ws1  = (const float*)d_in[4];
    const float* bs1  = (const float*)d_in[5];
    const float* Ws2  = (const float*)d_in[6];
    const float* bs2  = (const float*)d_in[7];
    const float* Ws3  = (const float*)d_in[8];
    const float* bs3  = (const float*)d_in[9];
    const float* Wt   = (const float*)d_in[10];
    const int*   ei   = (const int*)d_in[11];
    float* out = (float*)d_out;

    cudaFuncSetAttribute(k_mlp_mma, cudaFuncAttributeMaxDynamicSharedMemorySize,
                         MLP_SMEMW*4);

    k_prep_w<<<264,256>>>(Ws1,Ws2,Ws3,Wt);                                   // 0
    k_node_prep<<<NH/256,256>>>(X);                                          // 1
    k_mix<<<dim3(64,9),128>>>(0, 0);                                         // 2
    k_mlp_mma<<<NE/128,256,MLP_SMEMW*4>>>(attr, ewt, bs1, bs2, bs3, 0);      // 3 <- ncu
    k_zero_cnt<<<(NA+255)/256,256>>>();                                      // 4
    k_count<<<NE/256,256>>>(ei);                                             // 5
    k_scan<<<1,1024>>>();                                                    // 6
    k_place<<<NE/256,256>>>(ei);                                             // 7
    k_gather_update<<<NA,128>>>(ei, q);                                      // 8
    k_mix<<<dim3(64,9),128>>>(1, 3);                                         // 9
    k_upd_b<<<NH/256,256>>>(q, out);                                         // 10

    // layer 1 (CSR already built)
    k_node_prep<<<NH/256,256>>>(out);
    k_mix<<<dim3(64,9),128>>>(0, 6);
    k_mlp_mma<<<NE/128,256,MLP_SMEMW*4>>>(attr, ewt, bs1+128, bs2+256, bs3+384, 1);
    k_gather_update<<<NA,128>>>(ei, q);
    k_mix<<<dim3(64,9),128>>>(1, 9);
    k_upd_b<<<NH/256,256>>>(q, out);
}

// round 8
// speedup vs baseline: 2.6971x; 1.1015x over previous
#include <cuda_runtime.h>
#include <cstdint>
#include <cstddef>

#define NA 2048
#define HH 128
#define NE 32768
#define RR 32
#define NH (NA*HH)
#define CUT 4.5f

// ---------------- scratch (static device globals; no allocations) ----------------
__device__ float g_ea[NE*384];          // edge MLP output, layout [e][3][128] (float)
__device__ float g_Xn[NH*9];
__device__ float g_cA[9*NH];
__device__ float g_cM[9*NH];
__device__ float g_c2[9*NH];
__device__ float g_dXc[9*NH];
__device__ unsigned g_W1f[2*8*2*32*8];      // bf16 hi/lo fragment images
__device__ unsigned g_W2f[2*16*8*32*8];
__device__ unsigned g_W3f[2*24*16*32*8];    // W3 output-permuted: o' = c*128+h
__device__ float g_WtT[12*HH*HH];
__device__ int   g_cnt[NA];
__device__ int   g_cur[NA];
__device__ int   g_row[NA+1];
__device__ int   g_eord[NE];

typedef unsigned long long u64;
typedef unsigned u32;

// ---------------- generic helpers ----------------
__device__ __forceinline__ u64 pk(float a, float b){
    u64 r; asm("mov.b64 %0, {%1,%2};" : "=l"(r) : "f"(a), "f"(b)); return r;
}
__device__ __forceinline__ void upk(u64 v, float& a, float& b){
    asm("mov.b64 {%0,%1}, %2;" : "=f"(a), "=f"(b) : "l"(v));
}
__device__ __forceinline__ void fma2(u64& d, u64 a, u64 b){
    asm("fma.rn.f32x2 %0, %1, %2, %0;" : "+l"(d) : "l"(a), "l"(b));
}
__device__ __forceinline__ float siluf(float x){ return x / (1.f + __expf(-x)); }
__device__ __forceinline__ u32 prmt(u32 a, u32 b, u32 s){
    u32 d; asm("prmt.b32 %0,%1,%2,%3;" : "=r"(d) : "r"(a),"r"(b),"r"(s)); return d;
}

// split fp32 into packed (hi,lo) bf16 pair: low16 = hi bits, high16 = lo bits
__device__ __forceinline__ u32 pack_hl(float v){
    u32 u = __float_as_uint(v);
    float r = v - __uint_as_float(u & 0xFFFF0000u);   // exact residual
    return prmt(u, __float_as_uint(r), 0x7632);
}

// bf16 m16n8k16 mma: D(16x8) += A(16x16,row) * B(16x8,col)
__device__ __forceinline__ void mma16(float* d, const u32* a, const u32* b){
    asm volatile("mma.sync.aligned.m16n8k16.row.col.f32.bf16.bf16.f32 "
        "{%0,%1,%2,%3}, {%4,%5,%6,%7}, {%8,%9}, {%0,%1,%2,%3};"
        : "+f"(d[0]),"+f"(d[1]),"+f"(d[2]),"+f"(d[3])
        : "r"(a[0]),"r"(a[1]),"r"(a[2]),"r"(a[3]), "r"(b[0]),"r"(b[1]));
}

struct WF { uint4 h, l; };
__device__ __forceinline__ void ldwf(const uint4* __restrict__ W, int idx, WF& w){
    w.h = W[idx*2]; w.l = W[idx*2+1];
}

// one K=16 chunk, ONE m-tile, 8 edge-tiles; acts packed (hi,lo) u32 in smem
__device__ __forceinline__ void do_mma16_1(float (&d)[8][4], const WF& w,
                                           const u32* __restrict__ act, int pad,
                                           int ebase, int k0, int g, int t){
    const u32* ah = (const u32*)&w.h;
    const u32* al = (const u32*)&w.l;
    #pragma unroll
    for(int nt=0;nt<8;nt++){
        int e = ebase + nt*8 + g;
        uint2 q0 = *(const uint2*)&act[e*pad + k0 + 2*t];
        uint2 q1 = *(const uint2*)&act[e*pad + k0 + 2*t + 8];
        u32 bh[2], bl[2];
        bh[0]=prmt(q0.x,q0.y,0x5410); bl[0]=prmt(q0.x,q0.y,0x7632);
        bh[1]=prmt(q1.x,q1.y,0x5410); bl[1]=prmt(q1.x,q1.y,0x7632);
        mma16(d[nt],ah,bh); mma16(d[nt],ah,bl); mma16(d[nt],al,bh);
    }
}

// compact basis: {i0, a01, a02, a12, s00, s01, s02, s11, s12}
__device__ __forceinline__ void tocompact(const float* t, float s, float* c){
    float i0 = (t[0]+t[4]+t[8])*(1.f/3.f);
    c[0] = i0*s;
    c[1] = 0.5f*(t[1]-t[3])*s;
    c[2] = 0.5f*(t[2]-t[6])*s;
    c[3] = 0.5f*(t[5]-t[7])*s;
    c[4] = (t[0]-i0)*s;
    c[5] = 0.5f*(t[1]+t[3])*s;
    c[6] = 0.5f*(t[2]+t[6])*s;
    c[7] = (t[4]-i0)*s;
    c[8] = 0.5f*(t[5]+t[7])*s;
}
__device__ __forceinline__ void rec(const float* c, float* t){
    float i0=c[0], a01=c[1], a02=c[2], a12=c[3];
    float s00=c[4], s01=c[5], s02=c[6], s11=c[7], s12=c[8];
    t[0]=i0+s00;  t[1]=a01+s01; t[2]=a02+s02;
    t[3]=s01-a01; t[4]=i0+s11;  t[5]=a12+s12;
    t[6]=s02-a02; t[7]=s12-a12; t[8]=i0-s00-s11;
}
__device__ __forceinline__ void mmadd(const float* A, const float* B, float* C){
    #pragma unroll
    for(int i=0;i<3;i++){
        #pragma unroll
        for(int j=0;j<3;j++)
            C[i*3+j] += A[i*3+0]*B[0*3+j] + A[i*3+1]*B[1*3+j] + A[i*3+2]*B[2*3+j];
    }
}

// ---------------- weight prep: bf16 hi/lo fragment images + WtT ----------------
__device__ __forceinline__ void packw(const float* __restrict__ W, int stride,
                                      int r, int k, u32& hi, u32& lo){
    float w0=W[r*stride+k], w1=W[r*stride+k+1];
    u32 u0=__float_as_uint(w0);
    float r0=w0-__uint_as_float(u0&0xFFFF0000u);
    float r1=w1-__uint_as_float(__float_as_uint(w1)&0xFFFF0000u);
    hi = (u0>>16) | (__float_as_uint(w1)&0xFFFF0000u);
    lo = (__float_as_uint(r0)>>16) | (__float_as_uint(r1)&0xFFFF0000u);
}

__global__ void k_prep_w(const float* __restrict__ Ws1, const float* __restrict__ Ws2,
                         const float* __restrict__ Ws3, const float* __restrict__ Wt){
    int stride = gridDim.x*blockDim.x;
    int t0 = blockIdx.x*blockDim.x + threadIdx.x;
    for(int i=t0;i<2*8*2*32;i+=stride){
        int l=i>>9, r=i&511, ot=r>>6, r2=r&63, kc=r2>>5, lane=r2&31;
        int g=lane>>2, t=lane&3, o0=ot*16, kb=kc*16;
        const float* W = Ws1 + (size_t)l*128*32;
        u32 f[8];
        packw(W,32,o0+g,  kb+2*t,  f[0],f[4]);
        packw(W,32,o0+g+8,kb+2*t,  f[1],f[5]);
        packw(W,32,o0+g,  kb+2*t+8,f[2],f[6]);
        packw(W,32,o0+g+8,kb+2*t+8,f[3],f[7]);
        u32* dst = g_W1f + ((size_t)l*512 + (ot*2+kc)*32 + lane)*8;
        #pragma unroll
        for(int j=0;j<8;j++) dst[j]=f[j];
    }
    for(int i=t0;i<2*16*8*32;i+=stride){
        int l=i>>12, r=i&4095, ot=r>>8, r2=r&255, kc=r2>>5, lane=r2&31;
        int g=lane>>2, t=lane&3, o0=ot*16, kb=kc*16;
        const float* W = Ws2 + (size_t)l*256*128;
        u32 f[8];
        packw(W,128,o0+g,  kb+2*t,  f[0],f[4]);
        packw(W,128,o0+g+8,kb+2*t,  f[1],f[5]);
        packw(W,128,o0+g,  kb+2*t+8,f[2],f[6]);
        packw(W,128,o0+g+8,kb+2*t+8,f[3],f[7]);
        u32* dst = g_W2f + ((size_t)l*4096 + (ot*8+kc)*32 + lane)*8;
        #pragma unroll
        for(int j=0;j<8;j++) dst[j]=f[j];
    }
    for(int i=t0;i<2*24*16*32;i+=stride){
        int l=i/12288, r=i%12288, ot=r>>9, r2=r&511, kc=r2>>5, lane=r2&31;
        int g=lane>>2, t=lane&3, o0=ot*16, kb=kc*16;
        const float* W = Ws3 + (size_t)l*384*256;
        int rows[2] = { o0+g, o0+g+8 };
        u32 f[8];
        #pragma unroll
        for(int rr=0;rr<2;rr++){
            int op = rows[rr];
            int j = (op&127)*3 + (op>>7);
            packw(W,256,j,kb+2*t,  f[rr],  f[rr+4]);
            packw(W,256,j,kb+2*t+8,f[rr+2],f[rr+6]);
        }
        u32* dst = g_W3f + ((size_t)l*12288 + (ot*16+kc)*32 + lane)*8;
        #pragma unroll
        for(int j=0;j<8;j++) dst[j]=f[j];
    }
    for(int i=t0;i<12*128*128;i+=stride){
        int lm=i/16384, r=i%16384, g=r/128, hh=r%128;
        g_WtT[lm*16384 + hh*128 + g] = Wt[i];
    }
}

// ---------------- CSR build ----------------
__global__ void k_zero_cnt(){
    int i = blockIdx.x*blockDim.x + threadIdx.x;
    if(i<NA){ g_cnt[i]=0; g_cur[i]=0; }
}
__global__ void k_count(const int* __restrict__ ei){
    int e = blockIdx.x*blockDim.x + threadIdx.x;
    if(e<NE) atomicAdd(&g_cnt[ei[e]], 1);
}
__global__ void k_scan(){
    __shared__ int sh[1024];
    int t = threadIdx.x;
    int v0 = g_cnt[2*t], v1 = g_cnt[2*t+1];
    int s = v0+v1;
    sh[t]=s; __syncthreads();
    #pragma unroll
    for(int off=1; off<1024; off<<=1){
        int x = (t>=off)? sh[t-off] : 0;
        __syncthreads();
        sh[t] += x;
        __syncthreads();
    }
    int incl = sh[t];
    int excl = incl - s;
    g_row[2*t]   = excl;
    g_row[2*t+1] = excl + v0;
    if(t==1023) g_row[2048]=incl;
}
__global__ void k_place(const int* __restrict__ ei){
    int e = blockIdx.x*blockDim.x + threadIdx.x;
    if(e<NE){
        int s = ei[e];
        int p = atomicAdd(&g_cur[s],1);
        g_eord[g_row[s]+p] = e;
    }
}

// ---------------- node prep ----------------
__global__ void k_node_prep(const float* __restrict__ Xin){
    int idx = blockIdx.x*blockDim.x + threadIdx.x;
    if(idx>=NH) return;
    float t[9]; float nrm=0.f;
    #pragma unroll
    for(int r=0;r<9;r++){ t[r]=Xin[(size_t)idx*9+r]; nrm += t[r]*t[r]; }
    float inv = 1.f/(nrm+1.f);
    #pragma unroll
    for(int r=0;r<9;r++){ t[r]*=inv; g_Xn[(size_t)idx*9+r]=t[r]; }
    float c[9]; tocompact(t,1.f,c);
    #pragma unroll
    for(int d=0;d<9;d++) g_cA[d*NH+idx]=c[d];
}

// ---------------- channel mix (f32x2) ----------------
__global__ void __launch_bounds__(128) k_mix(int which, int wbase){
    __shared__ float sin_[32*128];
    const float* in  = which ? g_c2  : g_cA;
    float*       out = which ? g_dXc : g_cM;
    int d = blockIdx.y;
    int m = (d==0)?0:((d<4)?1:2);
    const float* W = g_WtT + (size_t)(wbase+m)*16384;
    int n0 = blockIdx.x*32;
    const float* src = in + (size_t)d*NH + (size_t)n0*HH;
    for(int i=threadIdx.x;i<1024;i+=128)
        ((float4*)sin_)[i] = ((const float4*)src)[i];
    __syncthreads();
    int w = threadIdx.x>>5, lane = threadIdx.x&31;
    u64 acc[8][2];
    #pragma unroll
    for(int i=0;i<8;i++){ acc[i][0]=0ull; acc[i][1]=0ull; }
    for(int k=0;k<128;k++){
        float4 wf = *(const float4*)&W[k*128 + lane*4];
        u64 w0=pk(wf.x,wf.y), w1=pk(wf.z,wf.w);
        #pragma unroll
        for(int i=0;i<8;i++){
            float v = sin_[(w*8+i)*128 + k];
            u64 vp = pk(v,v);
            fma2(acc[i][0],vp,w0); fma2(acc[i][1],vp,w1);
        }
    }
    float* dst = out + (size_t)d*NH + (size_t)n0*HH;
    #pragma unroll
    for(int i=0;i<8;i++){
        float4 o; upk(acc[i][0],o.x,o.y); upk(acc[i][1],o.z,o.w);
        *(float4*)&dst[(w*8+i)*HH + lane*4] = o;
    }
}

// ---------------- edge MLP: bf16 split mma, 16 warps (8 out-slices x 2 edge-halves)
#define H1PAD 136
#define H2PAD 264
#define APAD  40
#define MLP_SMEMW (128 + 128*H1PAD + 128*H2PAD)

__global__ void __launch_bounds__(512,1)
k_mlp_mma(const float* __restrict__ attr, const float* __restrict__ ewt,
          const float* __restrict__ b1, const float* __restrict__ b2,
          const float* __restrict__ b3raw, int l){
    extern __shared__ u32 smu[];
    float* cv = (float*)smu;
    u32* h1 = smu + 128;
    u32* h2 = smu + 128 + 128*H1PAD;
    u32* s_attr = h2;                  // alias, stage-1 only
    int tid = threadIdx.x;
    int warp = tid>>5, lane = tid&31;
    int g = lane>>2, t = lane&3;
    int hw = warp>>1;                  // output slice 0..7
    int ebase = (warp&1)*64;           // edge half
    int eblk = blockIdx.x*128;

    const uint4* W1 = (const uint4*)(g_W1f + (size_t)l*4096);
    const uint4* W2 = (const uint4*)(g_W2f + (size_t)l*32768);
    const uint4* W3 = (const uint4*)(g_W3f + (size_t)l*98304);

    // stage attr, pre-split packed
    for(int i=tid;i<1024;i+=512){
        int e=i>>3, k4=(i&7)<<2;
        float4 v = *(const float4*)&attr[(size_t)(eblk+e)*32 + k4];
        uint4 p = make_uint4(pack_hl(v.x),pack_hl(v.y),pack_hl(v.z),pack_hl(v.w));
        *(uint4*)&s_attr[e*APAD + k4] = p;
    }
    if(tid<128){
        float wv = ewt[eblk+tid];
        cv[tid] = (wv < CUT) ? 0.5f*(cosf(wv*(3.14159265358979f/CUT))+1.f) : 0.f;
    }
    __syncthreads();

    // ---- stage 1: 1 m-tile (outputs hw*16..+16), K=32 (2 chunks), 64 edges ----
    {
        float d[8][4];
        #pragma unroll
        for(int nt=0;nt<8;nt++){ d[nt][0]=d[nt][1]=d[nt][2]=d[nt][3]=0.f; }
        WF wa, wb;
        ldwf(W1, (hw*2+0)*32+lane, wa);
        ldwf(W1, (hw*2+1)*32+lane, wb);
        do_mma16_1(d, wa, s_attr, APAD, ebase, 0,  g, t);
        do_mma16_1(d, wb, s_attr, APAD, ebase, 16, g, t);
        int o = hw*16;
        float bA=b1[o+g], bB=b1[o+g+8];
        #pragma unroll
        for(int nt=0;nt<8;nt++){
            int e = ebase + nt*8 + 2*t;
            h1[e*H1PAD + o+g]       = pack_hl(siluf(d[nt][0]+bA));
            h1[(e+1)*H1PAD + o+g]   = pack_hl(siluf(d[nt][1]+bA));
            h1[e*H1PAD + o+g+8]     = pack_hl(siluf(d[nt][2]+bB));
            h1[(e+1)*H1PAD + o+g+8] = pack_hl(siluf(d[nt][3]+bB));
        }
    }
    __syncthreads();

    // ---- stage 2: 2 m-passes (outputs hw*32..+32), K=128 (8 chunks) ----
    #pragma unroll 1
    for(int mp=0; mp<2; mp++){
        float d[8][4];
        #pragma unroll
        for(int nt=0;nt<8;nt++){ d[nt][0]=d[nt][1]=d[nt][2]=d[nt][3]=0.f; }
        WF wa, wb;
        int base = (hw*2+mp)*8;
        ldwf(W2, (base+0)*32+lane, wa);
        #pragma unroll 1
        for(int kc=0;kc<8;kc+=2){
            ldwf(W2, (base+kc+1)*32+lane, wb);
            do_mma16_1(d, wa, h1, H1PAD, ebase, kc*16, g, t);
            if(kc+2<8) ldwf(W2, (base+kc+2)*32+lane, wa);
            do_mma16_1(d, wb, h1, H1PAD, ebase, (kc+1)*16, g, t);
        }
        int oo = hw*32 + mp*16;
        float bA=b2[oo+g], bB=b2[oo+g+8];
        #pragma unroll
        for(int nt=0;nt<8;nt++){
            int e = ebase + nt*8 + 2*t;
            h2[e*H2PAD + oo+g]       = pack_hl(siluf(d[nt][0]+bA));
            h2[(e+1)*H2PAD + oo+g]   = pack_hl(siluf(d[nt][1]+bA));
            h2[e*H2PAD + oo+g+8]     = pack_hl(siluf(d[nt][2]+bB));
            h2[(e+1)*H2PAD + oo+g+8] = pack_hl(siluf(d[nt][3]+bB));
        }
    }
    __syncthreads();

    // ---- stage 3: 3 m-passes (outputs hw*48..+48), K=256 (16 chunks) ----
    #pragma unroll 1
    for(int mp=0; mp<3; mp++){
        float d[8][4];
        #pragma unroll
        for(int nt=0;nt<8;nt++){ d[nt][0]=d[nt][1]=d[nt][2]=d[nt][3]=0.f; }
        WF wa, wb;
        int base = (hw*3+mp)*16;
        ldwf(W3, (base+0)*32+lane, wa);
        #pragma unroll 1
        for(int kc=0;kc<16;kc+=2){
            ldwf(W3, (base+kc+1)*32+lane, wb);
            do_mma16_1(d, wa, h2, H2PAD, ebase, kc*16, g, t);
            if(kc+2<16) ldwf(W3, (base+kc+2)*32+lane, wa);
            do_mma16_1(d, wb, h2, H2PAD, ebase, (kc+1)*16, g, t);
        }
        int oA = hw*48 + mp*16 + g, oB = oA + 8;
        float bA = b3raw[(oA&127)*3 + (oA>>7)];
        float bB = b3raw[(oB&127)*3 + (oB>>7)];
        #pragma unroll
        for(int nt=0;nt<8;nt++){
            int e0 = ebase + nt*8 + 2*t;
            float c0 = cv[e0], c1 = cv[e0+1];
            float* ep0 = g_ea + (size_t)(eblk+e0)*384;
            float* ep1 = g_ea + (size_t)(eblk+e0+1)*384;
            ep0[oA] = siluf(d[nt][0]+bA)*c0;
            ep1[oA] = siluf(d[nt][1]+bA)*c1;
            ep0[oB] = siluf(d[nt][2]+bB)*c0;
            ep1[oB] = siluf(d[nt][3]+bB)*c1;
        }
    }
}

// ---------------- gather segment-sum + O(3) node update ----------------
__global__ void __launch_bounds__(128) k_gather_update(const int* __restrict__ ei,
                                                       const float* __restrict__ q){
    int n = blockIdx.x;
    int h = threadIdx.x;
    int s = g_row[n], e1 = g_row[n+1];
    float cm[9];
    #pragma unroll
    for(int d=0;d<9;d++) cm[d]=0.f;
    for(int t=s;t<e1;t++){
        int e = g_eord[t];
        int dst = ei[NE + e];
        const float* ep = g_ea + (size_t)e*384;
        float a0=ep[h], a1=ep[128+h], a2=ep[256+h];
        int di = dst*HH + h;
        cm[0] += a0*g_cM[0*NH+di];
        cm[1] += a1*g_cM[1*NH+di];
        cm[2] += a1*g_cM[2*NH+di];
        cm[3] += a1*g_cM[3*NH+di];
        cm[4] += a2*g_cM[4*NH+di];
        cm[5] += a2*g_cM[5*NH+di];
        cm[6] += a2*g_cM[6*NH+di];
        cm[7] += a2*g_cM[7*NH+di];
        cm[8] += a2*g_cM[8*NH+di];
    }
    int idx = n*HH + h;
    float cy[9];
    #pragma unroll
    for(int d=0;d<9;d++) cy[d]=g_cM[d*NH+idx];
    float M[9], Y[9];
    rec(cm,M); rec(cy,Y);
    float AB[9];
    #pragma unroll
    for(int r=0;r<9;r++) AB[r]=0.f;
    mmadd(M,Y,AB); mmadd(Y,M,AB);
    float f = 1.f + 0.1f*q[n];
    float T[9]; float nrm=0.f;
    #pragma unroll
    for(int r=0;r<9;r++){ T[r]=f*AB[r]; nrm += T[r]*T[r]; }
    float inv = 1.f/(nrm+1.f);
    float c2[9]; tocompact(T,inv,c2);
    #pragma unroll
    for(int d=0;d<9;d++) g_c2[d*NH+idx]=c2[d];
}

// ---------------- final node update ----------------
__global__ void k_upd_b(const float* __restrict__ q, float* __restrict__ Xout){
    int idx = blockIdx.x*blockDim.x + threadIdx.x;
    if(idx>=NH) return;
    float c[9];
    #pragma unroll
    for(int d=0;d<9;d++) c[d]=g_dXc[d*NH+idx];
    float dx[9]; rec(c,dx);
    float f = 1.f + 0.1f*q[idx>>7];
    float D2[9];
    #pragma unroll
    for(int r=0;r<9;r++) D2[r]=0.f;
    mmadd(dx,dx,D2);
    #pragma unroll
    for(int r=0;r<9;r++)
        Xout[(size_t)idx*9+r] = g_Xn[(size_t)idx*9+r] + dx[r] + f*D2[r];
}

// ---------------- launcher (MLP at launch index 3 for the ncu window) ----------
extern "C" void kernel_launch(void* const* d_in, const int* in_sizes, int n_in,
                              void* d_out, int out_size){
    const float* X    = (const float*)d_in[0];
    const float* attr = (const float*)d_in[1];
    const float* ewt  = (const float*)d_in[2];
    const float* q    = (const float*)d_in[3];
    const float* Ws1  = (const float*)d_in[4];
    const float* bs1  = (const float*)d_in[5];
    const float* Ws2  = (const float*)d_in[6];
    const float* bs2  = (const float*)d_in[7];
    const float* Ws3  = (const float*)d_in[8];
    const float* bs3  = (const float*)d_in[9];
    const float* Wt   = (const float*)d_in[10];
    const int*   ei   = (const int*)d_in[11];
    float* out = (float*)d_out;

    cudaFuncSetAttribute(k_mlp_mma, cudaFuncAttributeMaxDynamicSharedMemorySize,
                         MLP_SMEMW*4);

    k_prep_w<<<264,256>>>(Ws1,Ws2,Ws3,Wt);                                   // 0
    k_node_prep<<<NH/256,256>>>(X);                                          // 1
    k_mix<<<dim3(64,9),128>>>(0, 0);                                         // 2
    k_mlp_mma<<<NE/128,512,MLP_SMEMW*4>>>(attr, ewt, bs1, bs2, bs3, 0);      // 3 <- ncu
    k_zero_cnt<<<(NA+255)/256,256>>>();                                      // 4
    k_count<<<NE/256,256>>>(ei);                                             // 5
    k_scan<<<1,1024>>>();                                                    // 6
    k_place<<<NE/256,256>>>(ei);                                             // 7
    k_gather_update<<<NA,128>>>(ei, q);                                      // 8
    k_mix<<<dim3(64,9),128>>>(1, 3);                                         // 9
    k_upd_b<<<NH/256,256>>>(q, out);                                         // 10

    // layer 1 (CSR already built)
    k_node_prep<<<NH/256,256>>>(out);
    k_mix<<<dim3(64,9),128>>>(0, 6);
    k_mlp_mma<<<NE/128,512,MLP_SMEMW*4>>>(attr, ewt, bs1+128, bs2+256, bs3+384, 1);
    k_gather_update<<<NA,128>>>(ei, q);
    k_mix<<<dim3(64,9),128>>>(1, 9);
    k_upd_b<<<NH/256,256>>>(q, out);
}

// round 9
// speedup vs baseline: 2.7865x; 1.0332x over previous
#include <cuda_runtime.h>
#include <cstdint>
#include <cstddef>

#define NA 2048
#define HH 128
#define NE 32768
#define RR 32
#define NH (NA*HH)
#define CUT 4.5f

// ---------------- scratch (static device globals; no allocations) ----------------
__device__ float g_ea[NE*384];          // edge MLP output, layout [e][3][128] (float)
__device__ float g_Xn[NH*9];
__device__ float g_cA[9*NH];
__device__ float g_cM[9*NH];
__device__ float g_c2[9*NH];
__device__ float g_dXc[9*NH];
__device__ unsigned g_W1f[2*8*2*32*8];      // bf16 hi/lo fragment images
__device__ unsigned g_W2f[2*16*8*32*8];
__device__ unsigned g_W3f[2*24*16*32*8];    // W3 output-permuted: o' = c*128+h
__device__ float g_WtT[12*HH*HH];
__device__ int   g_cnt[NA];
__device__ int   g_cur[NA];
__device__ int   g_row[NA+1];
__device__ int   g_eord[NE];

typedef unsigned long long u64;
typedef unsigned u32;

// ---------------- generic helpers ----------------
__device__ __forceinline__ u64 pk(float a, float b){
    u64 r; asm("mov.b64 %0, {%1,%2};" : "=l"(r) : "f"(a), "f"(b)); return r;
}
__device__ __forceinline__ void upk(u64 v, float& a, float& b){
    asm("mov.b64 {%0,%1}, %2;" : "=f"(a), "=f"(b) : "l"(v));
}
__device__ __forceinline__ void fma2(u64& d, u64 a, u64 b){
    asm("fma.rn.f32x2 %0, %1, %2, %0;" : "+l"(d) : "l"(a), "l"(b));
}
__device__ __forceinline__ float siluf(float x){ return x / (1.f + __expf(-x)); }

// split a pair of fp32 into packed bf16x2 (hi plane word, lo plane word)
__device__ __forceinline__ void split_pair(float x, float y, u32& hi, u32& lo){
    u32 ux=__float_as_uint(x), uy=__float_as_uint(y);
    float rx = x - __uint_as_float(ux&0xFFFF0000u);
    float ry = y - __uint_as_float(uy&0xFFFF0000u);
    hi = (ux>>16) | (uy & 0xFFFF0000u);
    lo = (__float_as_uint(rx)>>16) | (__float_as_uint(ry)&0xFFFF0000u);
}

// permuted word position within a 16-k chunk: words [w0,w4,w1,w5,w2,w6,w3,w7]
__device__ __forceinline__ int wpos(int w){ return 2*(w&3) + (w>>2); }

// store one fp32 value as bf16 hi/lo halves into the planes, k-index = o
__device__ __forceinline__ void st_hl(u32* hiP, u32* loP, int padw, int e, int o, float v){
    u32 u = __float_as_uint(v);
    float r = v - __uint_as_float(u&0xFFFF0000u);
    int w = (o&15)>>1;
    int idx = e*padw + (o>>4)*8 + wpos(w);
    unsigned short* hp = (unsigned short*)(hiP+idx) + (o&1);
    unsigned short* lp = (unsigned short*)(loP+idx) + (o&1);
    *hp = (unsigned short)(u>>16);
    *lp = (unsigned short)(__float_as_uint(r)>>16);
}

// bf16 m16n8k16 mma: D(16x8) += A(16x16,row) * B(16x8,col)
__device__ __forceinline__ void mma16(float* d, const u32* a, const u32* b){
    asm volatile("mma.sync.aligned.m16n8k16.row.col.f32.bf16.bf16.f32 "
        "{%0,%1,%2,%3}, {%4,%5,%6,%7}, {%8,%9}, {%0,%1,%2,%3};"
        : "+f"(d[0]),"+f"(d[1]),"+f"(d[2]),"+f"(d[3])
        : "r"(a[0]),"r"(a[1]),"r"(a[2]),"r"(a[3]), "r"(b[0]),"r"(b[1]));
}

struct WF { uint4 h, l; };
__device__ __forceinline__ void ldwf(const uint4* __restrict__ W, int idx, WF& w){
    w.h = W[idx*2]; w.l = W[idx*2+1];
}

// one K=16 chunk, ONE m-tile, 8 edge-tiles; B-frags read straight from hi/lo planes
__device__ __forceinline__ void do_mma16_1(float (&d)[8][4], const WF& w,
                                           const u32* __restrict__ hiP,
                                           const u32* __restrict__ loP,
                                           int padw, int ebase, int kc8, int g, int t){
    const u32* ah = (const u32*)&w.h;
    const u32* al = (const u32*)&w.l;
    #pragma unroll
    for(int nt=0;nt<8;nt++){
        int e = ebase + nt*8 + g;
        uint2 bh = *(const uint2*)&hiP[e*padw + kc8 + 2*t];
        uint2 bl = *(const uint2*)&loP[e*padw + kc8 + 2*t];
        mma16(d[nt],ah,(const u32*)&bh);
        mma16(d[nt],ah,(const u32*)&bl);
        mma16(d[nt],al,(const u32*)&bh);
    }
}

// compact basis: {i0, a01, a02, a12, s00, s01, s02, s11, s12}
__device__ __forceinline__ void tocompact(const float* t, float s, float* c){
    float i0 = (t[0]+t[4]+t[8])*(1.f/3.f);
    c[0] = i0*s;
    c[1] = 0.5f*(t[1]-t[3])*s;
    c[2] = 0.5f*(t[2]-t[6])*s;
    c[3] = 0.5f*(t[5]-t[7])*s;
    c[4] = (t[0]-i0)*s;
    c[5] = 0.5f*(t[1]+t[3])*s;
    c[6] = 0.5f*(t[2]+t[6])*s;
    c[7] = (t[4]-i0)*s;
    c[8] = 0.5f*(t[5]+t[7])*s;
}
__device__ __forceinline__ void rec(const float* c, float* t){
    float i0=c[0], a01=c[1], a02=c[2], a12=c[3];
    float s00=c[4], s01=c[5], s02=c[6], s11=c[7], s12=c[8];
    t[0]=i0+s00;  t[1]=a01+s01; t[2]=a02+s02;
    t[3]=s01-a01; t[4]=i0+s11;  t[5]=a12+s12;
    t[6]=s02-a02; t[7]=s12-a12; t[8]=i0-s00-s11;
}
__device__ __forceinline__ void mmadd(const float* A, const float* B, float* C){
    #pragma unroll
    for(int i=0;i<3;i++){
        #pragma unroll
        for(int j=0;j<3;j++)
            C[i*3+j] += A[i*3+0]*B[0*3+j] + A[i*3+1]*B[1*3+j] + A[i*3+2]*B[2*3+j];
    }
}

// ---------------- weight prep: bf16 hi/lo fragment images + WtT ----------------
__device__ __forceinline__ void packw(const float* __restrict__ W, int stride,
                                      int r, int k, u32& hi, u32& lo){
    float w0=W[r*stride+k], w1=W[r*stride+k+1];
    u32 u0=__float_as_uint(w0);
    float r0=w0-__uint_as_float(u0&0xFFFF0000u);
    float r1=w1-__uint_as_float(__float_as_uint(w1)&0xFFFF0000u);
    hi = (u0>>16) | (__float_as_uint(w1)&0xFFFF0000u);
    lo = (__float_as_uint(r0)>>16) | (__float_as_uint(r1)&0xFFFF0000u);
}

__global__ void k_prep_w(const float* __restrict__ Ws1, const float* __restrict__ Ws2,
                         const float* __restrict__ Ws3, const float* __restrict__ Wt){
    int stride = gridDim.x*blockDim.x;
    int t0 = blockIdx.x*blockDim.x + threadIdx.x;
    for(int i=t0;i<2*8*2*32;i+=stride){
        int l=i>>9, r=i&511, ot=r>>6, r2=r&63, kc=r2>>5, lane=r2&31;
        int g=lane>>2, t=lane&3, o0=ot*16, kb=kc*16;
        const float* W = Ws1 + (size_t)l*128*32;
        u32 f[8];
        packw(W,32,o0+g,  kb+2*t,  f[0],f[4]);
        packw(W,32,o0+g+8,kb+2*t,  f[1],f[5]);
        packw(W,32,o0+g,  kb+2*t+8,f[2],f[6]);
        packw(W,32,o0+g+8,kb+2*t+8,f[3],f[7]);
        u32* dst = g_W1f + ((size_t)l*512 + (ot*2+kc)*32 + lane)*8;
        #pragma unroll
        for(int j=0;j<8;j++) dst[j]=f[j];
    }
    for(int i=t0;i<2*16*8*32;i+=stride){
        int l=i>>12, r=i&4095, ot=r>>8, r2=r&255, kc=r2>>5, lane=r2&31;
        int g=lane>>2, t=lane&3, o0=ot*16, kb=kc*16;
        const float* W = Ws2 + (size_t)l*256*128;
        u32 f[8];
        packw(W,128,o0+g,  kb+2*t,  f[0],f[4]);
        packw(W,128,o0+g+8,kb+2*t,  f[1],f[5]);
        packw(W,128,o0+g,  kb+2*t+8,f[2],f[6]);
        packw(W,128,o0+g+8,kb+2*t+8,f[3],f[7]);
        u32* dst = g_W2f + ((size_t)l*4096 + (ot*8+kc)*32 + lane)*8;
        #pragma unroll
        for(int j=0;j<8;j++) dst[j]=f[j];
    }
    for(int i=t0;i<2*24*16*32;i+=stride){
        int l=i/12288, r=i%12288, ot=r>>9, r2=r&511, kc=r2>>5, lane=r2&31;
        int g=lane>>2, t=lane&3, o0=ot*16, kb=kc*16;
        const float* W = Ws3 + (size_t)l*384*256;
        int rows[2] = { o0+g, o0+g+8 };
        u32 f[8];
        #pragma unroll
        for(int rr=0;rr<2;rr++){
            int op = rows[rr];
            int j = (op&127)*3 + (op>>7);
            packw(W,256,j,kb+2*t,  f[rr],  f[rr+4]);
            packw(W,256,j,kb+2*t+8,f[rr+2],f[rr+6]);
        }
        u32* dst = g_W3f + ((size_t)l*12288 + (ot*16+kc)*32 + lane)*8;
        #pragma unroll
        for(int j=0;j<8;j++) dst[j]=f[j];
    }
    for(int i=t0;i<12*128*128;i+=stride){
        int lm=i/16384, r=i%16384, g=r/128, hh=r%128;
        g_WtT[lm*16384 + hh*128 + g] = Wt[i];
    }
}

// ---------------- CSR build ----------------
__global__ void k_zero_cnt(){
    int i = blockIdx.x*blockDim.x + threadIdx.x;
    if(i<NA){ g_cnt[i]=0; g_cur[i]=0; }
}
__global__ void k_count(const int* __restrict__ ei){
    int e = blockIdx.x*blockDim.x + threadIdx.x;
    if(e<NE) atomicAdd(&g_cnt[ei[e]], 1);
}
__global__ void k_scan(){
    __shared__ int sh[1024];
    int t = threadIdx.x;
    int v0 = g_cnt[2*t], v1 = g_cnt[2*t+1];
    int s = v0+v1;
    sh[t]=s; __syncthreads();
    #pragma unroll
    for(int off=1; off<1024; off<<=1){
        int x = (t>=off)? sh[t-off] : 0;
        __syncthreads();
        sh[t] += x;
        __syncthreads();
    }
    int incl = sh[t];
    int excl = incl - s;
    g_row[2*t]   = excl;
    g_row[2*t+1] = excl + v0;
    if(t==1023) g_row[2048]=incl;
}
__global__ void k_place(const int* __restrict__ ei){
    int e = blockIdx.x*blockDim.x + threadIdx.x;
    if(e<NE){
        int s = ei[e];
        int p = atomicAdd(&g_cur[s],1);
        g_eord[g_row[s]+p] = e;
    }
}

// ---------------- node prep ----------------
__global__ void k_node_prep(const float* __restrict__ Xin){
    int idx = blockIdx.x*blockDim.x + threadIdx.x;
    if(idx>=NH) return;
    float t[9]; float nrm=0.f;
    #pragma unroll
    for(int r=0;r<9;r++){ t[r]=Xin[(size_t)idx*9+r]; nrm += t[r]*t[r]; }
    float inv = 1.f/(nrm+1.f);
    #pragma unroll
    for(int r=0;r<9;r++){ t[r]*=inv; g_Xn[(size_t)idx*9+r]=t[r]; }
    float c[9]; tocompact(t,1.f,c);
    #pragma unroll
    for(int d=0;d<9;d++) g_cA[d*NH+idx]=c[d];
}

// ---------------- channel mix (f32x2) ----------------
__global__ void __launch_bounds__(128) k_mix(int which, int wbase){
    __shared__ float sin_[32*128];
    const float* in  = which ? g_c2  : g_cA;
    float*       out = which ? g_dXc : g_cM;
    int d = blockIdx.y;
    int m = (d==0)?0:((d<4)?1:2);
    const float* W = g_WtT + (size_t)(wbase+m)*16384;
    int n0 = blockIdx.x*32;
    const float* src = in + (size_t)d*NH + (size_t)n0*HH;
    for(int i=threadIdx.x;i<1024;i+=128)
        ((float4*)sin_)[i] = ((const float4*)src)[i];
    __syncthreads();
    int w = threadIdx.x>>5, lane = threadIdx.x&31;
    u64 acc[8][2];
    #pragma unroll
    for(int i=0;i<8;i++){ acc[i][0]=0ull; acc[i][1]=0ull; }
    for(int k=0;k<128;k++){
        float4 wf = *(const float4*)&W[k*128 + lane*4];
        u64 w0=pk(wf.x,wf.y), w1=pk(wf.z,wf.w);
        #pragma unroll
        for(int i=0;i<8;i++){
            float v = sin_[(w*8+i)*128 + k];
            u64 vp = pk(v,v);
            fma2(acc[i][0],vp,w0); fma2(acc[i][1],vp,w1);
        }
    }
    float* dst = out + (size_t)d*NH + (size_t)n0*HH;
    #pragma unroll
    for(int i=0;i<8;i++){
        float4 o; upk(acc[i][0],o.x,o.y); upk(acc[i][1],o.z,o.w);
        *(float4*)&dst[(w*8+i)*HH + lane*4] = o;
    }
}

// ---------------- edge MLP: bf16 split mma, hi/lo planes, permuted words ------
// plane pads in u32 words, all ≡ 8 (mod 32) -> conflict-free LDS.64
#define A_PADW  40
#define H1_PADW 72
#define H2_PADW 136
#define MLP_SMEMW (128 + 2*128*H1_PADW + 2*128*H2_PADW)

__global__ void __launch_bounds__(512,1)
k_mlp_mma(const float* __restrict__ attr, const float* __restrict__ ewt,
          const float* __restrict__ b1, const float* __restrict__ b2,
          const float* __restrict__ b3raw, int l){
    extern __shared__ u32 smu[];
    float* cv = (float*)smu;
    u32* h1h = smu + 128;
    u32* h1l = h1h + 128*H1_PADW;
    u32* h2h = h1l + 128*H1_PADW;
    u32* h2l = h2h + 128*H2_PADW;
    u32* aah = h2h;                    // attr planes alias h2 (stage-1 only)
    u32* aal = h2l;
    int tid = threadIdx.x;
    int warp = tid>>5, lane = tid&31;
    int g = lane>>2, t = lane&3;
    int hw = warp>>1;                  // output slice 0..7
    int ebase = (warp&1)*64;           // edge half
    int eblk = blockIdx.x*128;

    const uint4* W1 = (const uint4*)(g_W1f + (size_t)l*4096);
    const uint4* W2 = (const uint4*)(g_W2f + (size_t)l*32768);
    const uint4* W3 = (const uint4*)(g_W3f + (size_t)l*98304);

    // stage attr into hi/lo planes with permuted word order
    for(int i=tid;i<1024;i+=512){
        int e=i>>3, k4=(i&7)<<2;           // k4 in {0,4,...,28}
        float4 v = *(const float4*)&attr[(size_t)(eblk+e)*32 + k4];
        int kc = k4>>4;
        int lw = (k4&15)>>1;               // even: 0,2,4,6
        u32 hi0,lo0,hi1,lo1;
        split_pair(v.x,v.y,hi0,lo0);
        split_pair(v.z,v.w,hi1,lo1);
        int base = e*A_PADW + kc*8;
        aah[base + wpos(lw)]   = hi0;
        aah[base + wpos(lw+1)] = hi1;
        aal[base + wpos(lw)]   = lo0;
        aal[base + wpos(lw+1)] = lo1;
    }
    if(tid<128){
        float wv = ewt[eblk+tid];
        cv[tid] = (wv < CUT) ? 0.5f*(cosf(wv*(3.14159265358979f/CUT))+1.f) : 0.f;
    }
    __syncthreads();

    // ---- stage 1: 1 m-tile (outputs hw*16..+16), K=32 (2 chunks), 64 edges ----
    {
        float d[8][4];
        #pragma unroll
        for(int nt=0;nt<8;nt++){ d[nt][0]=d[nt][1]=d[nt][2]=d[nt][3]=0.f; }
        WF wa, wb;
        ldwf(W1, (hw*2+0)*32+lane, wa);
        ldwf(W1, (hw*2+1)*32+lane, wb);
        do_mma16_1(d, wa, aah, aal, A_PADW, ebase, 0, g, t);
        do_mma16_1(d, wb, aah, aal, A_PADW, ebase, 8, g, t);
        int o = hw*16;
        float bA=b1[o+g], bB=b1[o+g+8];
        #pragma unroll
        for(int nt=0;nt<8;nt++){
            int e = ebase + nt*8 + 2*t;
            st_hl(h1h,h1l,H1_PADW,e,  o+g,  siluf(d[nt][0]+bA));
            st_hl(h1h,h1l,H1_PADW,e+1,o+g,  siluf(d[nt][1]+bA));
            st_hl(h1h,h1l,H1_PADW,e,  o+g+8,siluf(d[nt][2]+bB));
            st_hl(h1h,h1l,H1_PADW,e+1,o+g+8,siluf(d[nt][3]+bB));
        }
    }
    __syncthreads();

    // ---- stage 2: 2 m-passes (outputs hw*32..+32), K=128 (8 chunks) ----
    #pragma unroll 1
    for(int mp=0; mp<2; mp++){
        float d[8][4];
        #pragma unroll
        for(int nt=0;nt<8;nt++){ d[nt][0]=d[nt][1]=d[nt][2]=d[nt][3]=0.f; }
        WF wa, wb;
        int base = (hw*2+mp)*8;
        ldwf(W2, (base+0)*32+lane, wa);
        #pragma unroll 1
        for(int kc=0;kc<8;kc+=2){
            ldwf(W2, (base+kc+1)*32+lane, wb);
            do_mma16_1(d, wa, h1h, h1l, H1_PADW, ebase, kc*8, g, t);
            if(kc+2<8) ldwf(W2, (base+kc+2)*32+lane, wa);
            do_mma16_1(d, wb, h1h, h1l, H1_PADW, ebase, (kc+1)*8, g, t);
        }
        int oo = hw*32 + mp*16;
        float bA=b2[oo+g], bB=b2[oo+g+8];
        #pragma unroll
        for(int nt=0;nt<8;nt++){
            int e = ebase + nt*8 + 2*t;
            st_hl(h2h,h2l,H2_PADW,e,  oo+g,  siluf(d[nt][0]+bA));
            st_hl(h2h,h2l,H2_PADW,e+1,oo+g,  siluf(d[nt][1]+bA));
            st_hl(h2h,h2l,H2_PADW,e,  oo+g+8,siluf(d[nt][2]+bB));
            st_hl(h2h,h2l,H2_PADW,e+1,oo+g+8,siluf(d[nt][3]+bB));
        }
    }
    __syncthreads();

    // ---- stage 3: 3 m-passes (outputs hw*48..+48), K=256 (16 chunks) ----
    #pragma unroll 1
    for(int mp=0; mp<3; mp++){
        float d[8][4];
        #pragma unroll
        for(int nt=0;nt<8;nt++){ d[nt][0]=d[nt][1]=d[nt][2]=d[nt][3]=0.f; }
        WF wa, wb;
        int base = (hw*3+mp)*16;
        ldwf(W3, (base+0)*32+lane, wa);
        #pragma unroll 1
        for(int kc=0;kc<16;kc+=2){
            ldwf(W3, (base+kc+1)*32+lane, wb);
            do_mma16_1(d, wa, h2h, h2l, H2_PADW, ebase, kc*8, g, t);
            if(kc+2<16) ldwf(W3, (base+kc+2)*32+lane, wa);
            do_mma16_1(d, wb, h2h, h2l, H2_PADW, ebase, (kc+1)*8, g, t);
        }
        int oA = hw*48 + mp*16 + g, oB = oA + 8;
        float bA = b3raw[(oA&127)*3 + (oA>>7)];
        float bB = b3raw[(oB&127)*3 + (oB>>7)];
        #pragma unroll
        for(int nt=0;nt<8;nt++){
            int e0 = ebase + nt*8 + 2*t;
            float c0 = cv[e0], c1 = cv[e0+1];
            float* ep0 = g_ea + (size_t)(eblk+e0)*384;
            float* ep1 = g_ea + (size_t)(eblk+e0+1)*384;
            ep0[oA] = siluf(d[nt][0]+bA)*c0;
            ep1[oA] = siluf(d[nt][1]+bA)*c1;
            ep0[oB] = siluf(d[nt][2]+bB)*c0;
            ep1[oB] = siluf(d[nt][3]+bB)*c1;
        }
    }
}

// ---------------- gather segment-sum + O(3) node update ----------------
__global__ void __launch_bounds__(128) k_gather_update(const int* __restrict__ ei,
                                                       const float* __restrict__ q){
    int n = blockIdx.x;
    int h = threadIdx.x;
    int s = g_row[n], e1 = g_row[n+1];
    float cm[9];
    #pragma unroll
    for(int d=0;d<9;d++) cm[d]=0.f;
    for(int t=s;t<e1;t++){
        int e = g_eord[t];
        int dst = ei[NE + e];
        const float* ep = g_ea + (size_t)e*384;
        float a0=ep[h], a1=ep[128+h], a2=ep[256+h];
        int di = dst*HH + h;
        cm[0] += a0*g_cM[0*NH+di];
        cm[1] += a1*g_cM[1*NH+di];
        cm[2] += a1*g_cM[2*NH+di];
        cm[3] += a1*g_cM[3*NH+di];
        cm[4] += a2*g_cM[4*NH+di];
        cm[5] += a2*g_cM[5*NH+di];
        cm[6] += a2*g_cM[6*NH+di];
        cm[7] += a2*g_cM[7*NH+di];
        cm[8] += a2*g_cM[8*NH+di];
    }
    int idx = n*HH + h;
    float cy[9];
    #pragma unroll
    for(int d=0;d<9;d++) cy[d]=g_cM[d*NH+idx];
    float M[9], Y[9];
    rec(cm,M); rec(cy,Y);
    float AB[9];
    #pragma unroll
    for(int r=0;r<9;r++) AB[r]=0.f;
    mmadd(M,Y,AB); mmadd(Y,M,AB);
    float f = 1.f + 0.1f*q[n];
    float T[9]; float nrm=0.f;
    #pragma unroll
    for(int r=0;r<9;r++){ T[r]=f*AB[r]; nrm += T[r]*T[r]; }
    float inv = 1.f/(nrm+1.f);
    float c2[9]; tocompact(T,inv,c2);
    #pragma unroll
    for(int d=0;d<9;d++) g_c2[d*NH+idx]=c2[d];
}

// ---------------- final node update ----------------
__global__ void k_upd_b(const float* __restrict__ q, float* __restrict__ Xout){
    int idx = blockIdx.x*blockDim.x + threadIdx.x;
    if(idx>=NH) return;
    float c[9];
    #pragma unroll
    for(int d=0;d<9;d++) c[d]=g_dXc[d*NH+idx];
    float dx[9]; rec(c,dx);
    float f = 1.f + 0.1f*q[idx>>7];
    float D2[9];
    #pragma unroll
    for(int r=0;r<9;r++) D2[r]=0.f;
    mmadd(dx,dx,D2);
    #pragma unroll
    for(int r=0;r<9;r++)
        Xout[(size_t)idx*9+r] = g_Xn[(size_t)idx*9+r] + dx[r] + f*D2[r];
}

// ---------------- launcher (MLP at launch index 3 for the ncu window) ----------
extern "C" void kernel_launch(void* const* d_in, const int* in_sizes, int n_in,
                              void* d_out, int out_size){
    const float* X    = (const float*)d_in[0];
    const float* attr = (const float*)d_in[1];
    const float* ewt  = (const float*)d_in[2];
    const float* q    = (const float*)d_in[3];
    const float* Ws1  = (const float*)d_in[4];
    const float* bs1  = (const float*)d_in[5];
    const float* Ws2  = (const float*)d_in[6];
    const float* bs2  = (const float*)d_in[7];
    const float* Ws3  = (const float*)d_in[8];
    const float* bs3  = (const float*)d_in[9];
    const float* Wt   = (const float*)d_in[10];
    const int*   ei   = (const int*)d_in[11];
    float* out = (float*)d_out;

    cudaFuncSetAttribute(k_mlp_mma, cudaFuncAttributeMaxDynamicSharedMemorySize,
                         MLP_SMEMW*4);

    k_prep_w<<<264,256>>>(Ws1,Ws2,Ws3,Wt);                                   // 0
    k_node_prep<<<NH/256,256>>>(X);                                          // 1
    k_mix<<<dim3(64,9),128>>>(0, 0);                                         // 2
    k_mlp_mma<<<NE/128,512,MLP_SMEMW*4>>>(attr, ewt, bs1, bs2, bs3, 0);      // 3 <- ncu
    k_zero_cnt<<<(NA+255)/256,256>>>();                                      // 4
    k_count<<<NE/256,256>>>(ei);                                             // 5
    k_scan<<<1,1024>>>();                                                    // 6
    k_place<<<NE/256,256>>>(ei);                                             // 7
    k_gather_update<<<NA,128>>>(ei, q);                                      // 8
    k_mix<<<dim3(64,9),128>>>(1, 3);                                         // 9
    k_upd_b<<<NH/256,256>>>(q, out);                                         // 10

    // layer 1 (CSR already built)
    k_node_prep<<<NH/256,256>>>(out);
    k_mix<<<dim3(64,9),128>>>(0, 6);
    k_mlp_mma<<<NE/128,512,MLP_SMEMW*4>>>(attr, ewt, bs1+128, bs2+256, bs3+384, 1);
    k_gather_update<<<NA,128>>>(ei, q);
    k_mix<<<dim3(64,9),128>>>(1, 9);
    k_upd_b<<<NH/256,256>>>(q, out);
}